// round 1
// baseline (speedup 1.0000x reference)
#include <cuda_runtime.h>
#include <cuda_bf16.h>
#include <math.h>

// ---------------- problem constants ----------------
#define BATCH   2
#define SEQ     2048
#define DMODEL  1024
#define NHEADS  16
#define DHEAD   64
#define FFDIM   4096
#define MTOK    (BATCH * SEQ)          // 4096 token rows

// ---------------- scratch (device globals; no allocation) ----------------
__device__ float g_H  [MTOK * DMODEL];   // LN output (reused for LN1 and LN2)
__device__ float g_Q  [MTOK * DMODEL];
__device__ float g_K  [MTOK * DMODEL];
__device__ float g_V  [MTOK * DMODEL];
__device__ float g_CTX[MTOK * DMODEL];
__device__ float g_X2 [MTOK * DMODEL];   // residual-1 output
__device__ float g_FF [MTOK * FFDIM];    // FF hidden

// =======================================================================
// LayerNorm: one block per row of 1024, 256 threads, float4 per thread
// =======================================================================
__global__ void ln_kernel(const float* __restrict__ x,
                          const float* __restrict__ gamma,
                          const float* __restrict__ beta,
                          float* __restrict__ out)
{
    int row = blockIdx.x;
    int tid = threadIdx.x;
    const float* xr = x + (size_t)row * DMODEL;

    float4 v = *(const float4*)(xr + tid * 4);
    float s  = v.x + v.y + v.z + v.w;
    float sq = v.x*v.x + v.y*v.y + v.z*v.z + v.w*v.w;

    // warp reduce
    #pragma unroll
    for (int off = 16; off > 0; off >>= 1) {
        s  += __shfl_xor_sync(0xffffffffu, s,  off);
        sq += __shfl_xor_sync(0xffffffffu, sq, off);
    }
    __shared__ float ssum[8], ssq[8];
    int wid = tid >> 5, lane = tid & 31;
    if (lane == 0) { ssum[wid] = s; ssq[wid] = sq; }
    __syncthreads();
    float tot = 0.f, totq = 0.f;
    #pragma unroll
    for (int w = 0; w < 8; w++) { tot += ssum[w]; totq += ssq[w]; }

    const float invN = 1.0f / (float)DMODEL;
    float mean = tot * invN;
    float var  = totq * invN - mean * mean;
    float inv  = rsqrtf(var + 1e-5f);

    float4 g4 = *(const float4*)(gamma + tid * 4);
    float4 b4 = *(const float4*)(beta  + tid * 4);
    float4 o;
    o.x = (v.x - mean) * inv * g4.x + b4.x;
    o.y = (v.y - mean) * inv * g4.y + b4.y;
    o.z = (v.z - mean) * inv * g4.z + b4.z;
    o.w = (v.w - mean) * inv * g4.w + b4.w;
    *(float4*)(out + (size_t)row * DMODEL + tid * 4) = o;
}

// =======================================================================
// SGEMM: C[M,N] = A[M,K] @ B[K,N] + bias (+resid) (relu)
// BM=BN=128, BK=16, 256 threads, 8x8 micro-tile per thread
// =======================================================================
#define BM 128
#define BN 128
#define BK 16

__global__ __launch_bounds__(256, 2)
void gemm_kernel(const float* __restrict__ A, const float* __restrict__ Bw,
                 const float* __restrict__ bias, const float* __restrict__ resid,
                 float* __restrict__ C, int M, int N, int K, int relu)
{
    __shared__ float As[BK][BM];     // transposed A tile: As[k][m]
    __shared__ float Bs[BK][BN];     // Bs[k][n]

    int tid = threadIdx.x;
    int tx = tid & 15;               // 0..15 -> n micro
    int ty = tid >> 4;               // 0..15 -> m micro
    int bm = blockIdx.y * BM;
    int bn = blockIdx.x * BN;

    // A load mapping: 128 rows x 16 cols, 8 floats / thread
    int a_m = tid >> 1;              // 0..127
    int a_k = (tid & 1) * 8;         // 0 or 8
    // B load mapping: 16 rows x 128 cols, 8 floats / thread
    int b_k = tid >> 4;              // 0..15
    int b_n = (tid & 15) * 8;

    float acc[8][8];
    #pragma unroll
    for (int i = 0; i < 8; i++)
        #pragma unroll
        for (int j = 0; j < 8; j++) acc[i][j] = 0.f;

    for (int k0 = 0; k0 < K; k0 += BK) {
        const float* ap = A + (size_t)(bm + a_m) * K + k0 + a_k;
        float4 a0 = *(const float4*)(ap);
        float4 a1 = *(const float4*)(ap + 4);
        As[a_k+0][a_m] = a0.x; As[a_k+1][a_m] = a0.y;
        As[a_k+2][a_m] = a0.z; As[a_k+3][a_m] = a0.w;
        As[a_k+4][a_m] = a1.x; As[a_k+5][a_m] = a1.y;
        As[a_k+6][a_m] = a1.z; As[a_k+7][a_m] = a1.w;

        const float* bp = Bw + (size_t)(k0 + b_k) * N + bn + b_n;
        *(float4*)&Bs[b_k][b_n]     = *(const float4*)(bp);
        *(float4*)&Bs[b_k][b_n + 4] = *(const float4*)(bp + 4);
        __syncthreads();

        #pragma unroll
        for (int k = 0; k < BK; k++) {
            float af[8], bf[8];
            *(float4*)(af)     = *(const float4*)&As[k][ty*8];
            *(float4*)(af + 4) = *(const float4*)&As[k][ty*8 + 4];
            *(float4*)(bf)     = *(const float4*)&Bs[k][tx*8];
            *(float4*)(bf + 4) = *(const float4*)&Bs[k][tx*8 + 4];
            #pragma unroll
            for (int i = 0; i < 8; i++)
                #pragma unroll
                for (int j = 0; j < 8; j++)
                    acc[i][j] = fmaf(af[i], bf[j], acc[i][j]);
        }
        __syncthreads();
    }

    // epilogue
    float4 bia0 = *(const float4*)(bias + bn + tx*8);
    float4 bia1 = *(const float4*)(bias + bn + tx*8 + 4);
    #pragma unroll
    for (int i = 0; i < 8; i++) {
        int row = bm + ty*8 + i;
        float* crow = C + (size_t)row * N + bn + tx*8;
        float4 c0, c1;
        c0.x = acc[i][0] + bia0.x; c0.y = acc[i][1] + bia0.y;
        c0.z = acc[i][2] + bia0.z; c0.w = acc[i][3] + bia0.w;
        c1.x = acc[i][4] + bia1.x; c1.y = acc[i][5] + bia1.y;
        c1.z = acc[i][6] + bia1.z; c1.w = acc[i][7] + bia1.w;
        if (resid) {
            const float* rrow = resid + (size_t)row * N + bn + tx*8;
            float4 r0 = *(const float4*)(rrow);
            float4 r1 = *(const float4*)(rrow + 4);
            c0.x += r0.x; c0.y += r0.y; c0.z += r0.z; c0.w += r0.w;
            c1.x += r1.x; c1.y += r1.y; c1.z += r1.z; c1.w += r1.w;
        }
        if (relu) {
            c0.x = fmaxf(c0.x, 0.f); c0.y = fmaxf(c0.y, 0.f);
            c0.z = fmaxf(c0.z, 0.f); c0.w = fmaxf(c0.w, 0.f);
            c1.x = fmaxf(c1.x, 0.f); c1.y = fmaxf(c1.y, 0.f);
            c1.z = fmaxf(c1.z, 0.f); c1.w = fmaxf(c1.w, 0.f);
        }
        *(float4*)(crow)     = c0;
        *(float4*)(crow + 4) = c1;
    }
}

// =======================================================================
// Flash attention (fp32, online softmax), one block = (b, h, 64 q-rows)
// smem: Qs[64][68], Kst[64 d][68 keys], Vs[64][68], Ps[64][68]  (dynamic)
// =======================================================================
#define ATP 68
#define NEG_BIG (-1e30f)

__global__ __launch_bounds__(256, 2)
void attn_kernel(const float* __restrict__ Q, const float* __restrict__ K,
                 const float* __restrict__ V, const int* __restrict__ mask,
                 float* __restrict__ O)
{
    extern __shared__ float sm[];
    float* Qs  = sm;                 // [64][68]  (q-row major)
    float* Kst = Qs  + 64 * ATP;     // [64][68]  (d major, key minor)
    float* Vs  = Kst + 64 * ATP;     // [64][68]  (key major, d minor)
    float* Ps  = Vs  + 64 * ATP;     // [64][68]  (q-row major, key minor)
    __shared__ int msk[64];

    int tid = threadIdx.x;
    int tx = tid & 15;               // key / d column group
    int ty = tid >> 4;               // q row group
    int q0 = blockIdx.x * 64;
    int h  = blockIdx.y;
    int b  = blockIdx.z;

    // load Q tile (64 x 64)
    {
        int r  = tid >> 2;
        int d0 = (tid & 3) * 16;
        const float* qp = Q + ((size_t)((b*SEQ + q0 + r)*NHEADS + h))*DHEAD + d0;
        #pragma unroll
        for (int i = 0; i < 4; i++)
            *(float4*)&Qs[r*ATP + d0 + i*4] = *(const float4*)(qp + i*4);
    }

    float m_i[4] = {NEG_BIG, NEG_BIG, NEG_BIG, NEG_BIG};
    float l_i[4] = {0.f, 0.f, 0.f, 0.f};
    float o[4][4];
    #pragma unroll
    for (int i = 0; i < 4; i++)
        #pragma unroll
        for (int j = 0; j < 4; j++) o[i][j] = 0.f;

    for (int t0 = 0; t0 < SEQ; t0 += 64) {
        // load K (transposed to d-major) and V tiles
        {
            int kr = tid >> 2;
            int d0 = (tid & 3) * 16;
            const float* kp = K + ((size_t)((b*SEQ + t0 + kr)*NHEADS + h))*DHEAD + d0;
            #pragma unroll
            for (int i = 0; i < 4; i++) {
                float4 kv = *(const float4*)(kp + i*4);
                Kst[(d0+i*4+0)*ATP + kr] = kv.x;
                Kst[(d0+i*4+1)*ATP + kr] = kv.y;
                Kst[(d0+i*4+2)*ATP + kr] = kv.z;
                Kst[(d0+i*4+3)*ATP + kr] = kv.w;
            }
            const float* vp = V + ((size_t)((b*SEQ + t0 + kr)*NHEADS + h))*DHEAD + d0;
            #pragma unroll
            for (int i = 0; i < 4; i++)
                *(float4*)&Vs[kr*ATP + d0 + i*4] = *(const float4*)(vp + i*4);
            if (tid < 64) msk[tid] = mask[b*SEQ + t0 + tid];
        }
        __syncthreads();

        // scores: s[i][j] = sum_d Qs[ty*4+i][d] * Kst[d][tx*4+j]
        float s[4][4];
        #pragma unroll
        for (int i = 0; i < 4; i++)
            #pragma unroll
            for (int j = 0; j < 4; j++) s[i][j] = 0.f;

        #pragma unroll 8
        for (int d = 0; d < DHEAD; d++) {
            float4 kv = *(const float4*)&Kst[d*ATP + tx*4];
            float q0v = Qs[(ty*4+0)*ATP + d];
            float q1v = Qs[(ty*4+1)*ATP + d];
            float q2v = Qs[(ty*4+2)*ATP + d];
            float q3v = Qs[(ty*4+3)*ATP + d];
            s[0][0] = fmaf(q0v, kv.x, s[0][0]); s[0][1] = fmaf(q0v, kv.y, s[0][1]);
            s[0][2] = fmaf(q0v, kv.z, s[0][2]); s[0][3] = fmaf(q0v, kv.w, s[0][3]);
            s[1][0] = fmaf(q1v, kv.x, s[1][0]); s[1][1] = fmaf(q1v, kv.y, s[1][1]);
            s[1][2] = fmaf(q1v, kv.z, s[1][2]); s[1][3] = fmaf(q1v, kv.w, s[1][3]);
            s[2][0] = fmaf(q2v, kv.x, s[2][0]); s[2][1] = fmaf(q2v, kv.y, s[2][1]);
            s[2][2] = fmaf(q2v, kv.z, s[2][2]); s[2][3] = fmaf(q2v, kv.w, s[2][3]);
            s[3][0] = fmaf(q3v, kv.x, s[3][0]); s[3][1] = fmaf(q3v, kv.y, s[3][1]);
            s[3][2] = fmaf(q3v, kv.z, s[3][2]); s[3][3] = fmaf(q3v, kv.w, s[3][3]);
        }

        const float scale = 0.125f;   // 1/sqrt(64)
        #pragma unroll
        for (int i = 0; i < 4; i++)
            #pragma unroll
            for (int j = 0; j < 4; j++) {
                float sc = s[i][j] * scale;
                if (msk[tx*4 + j] == 0) sc = NEG_BIG;
                s[i][j] = sc;
            }

        // online softmax per q-row (reduce over the 16 tx lanes)
        #pragma unroll
        for (int i = 0; i < 4; i++) {
            float mn = fmaxf(fmaxf(s[i][0], s[i][1]), fmaxf(s[i][2], s[i][3]));
            #pragma unroll
            for (int off = 8; off > 0; off >>= 1)
                mn = fmaxf(mn, __shfl_xor_sync(0xffffffffu, mn, off));
            mn = fmaxf(mn, m_i[i]);

            float factor = __expf(m_i[i] - mn);   // m_i=-1e30 -> underflow 0
            float rowsum = 0.f;
            #pragma unroll
            for (int j = 0; j < 4; j++) {
                float p = __expf(s[i][j] - mn);
                Ps[(ty*4 + i)*ATP + tx*4 + j] = p;
                rowsum += p;
            }
            #pragma unroll
            for (int off = 8; off > 0; off >>= 1)
                rowsum += __shfl_xor_sync(0xffffffffu, rowsum, off);

            l_i[i] = l_i[i] * factor + rowsum;
            m_i[i] = mn;
            #pragma unroll
            for (int j = 0; j < 4; j++) o[i][j] *= factor;
        }
        __syncthreads();

        // o += Ps @ Vs
        #pragma unroll 8
        for (int tk = 0; tk < 64; tk++) {
            float4 vv = *(const float4*)&Vs[tk*ATP + tx*4];
            float p0 = Ps[(ty*4+0)*ATP + tk];
            float p1 = Ps[(ty*4+1)*ATP + tk];
            float p2 = Ps[(ty*4+2)*ATP + tk];
            float p3 = Ps[(ty*4+3)*ATP + tk];
            o[0][0] = fmaf(p0, vv.x, o[0][0]); o[0][1] = fmaf(p0, vv.y, o[0][1]);
            o[0][2] = fmaf(p0, vv.z, o[0][2]); o[0][3] = fmaf(p0, vv.w, o[0][3]);
            o[1][0] = fmaf(p1, vv.x, o[1][0]); o[1][1] = fmaf(p1, vv.y, o[1][1]);
            o[1][2] = fmaf(p1, vv.z, o[1][2]); o[1][3] = fmaf(p1, vv.w, o[1][3]);
            o[2][0] = fmaf(p2, vv.x, o[2][0]); o[2][1] = fmaf(p2, vv.y, o[2][1]);
            o[2][2] = fmaf(p2, vv.z, o[2][2]); o[2][3] = fmaf(p2, vv.w, o[2][3]);
            o[3][0] = fmaf(p3, vv.x, o[3][0]); o[3][1] = fmaf(p3, vv.y, o[3][1]);
            o[3][2] = fmaf(p3, vv.z, o[3][2]); o[3][3] = fmaf(p3, vv.w, o[3][3]);
        }
        __syncthreads();
    }

    // write ctx
    #pragma unroll
    for (int i = 0; i < 4; i++) {
        float inv = 1.0f / l_i[i];
        int srow = q0 + ty*4 + i;
        float* op = O + ((size_t)((b*SEQ + srow)*NHEADS + h))*DHEAD + tx*4;
        float4 ov;
        ov.x = o[i][0]*inv; ov.y = o[i][1]*inv; ov.z = o[i][2]*inv; ov.w = o[i][3]*inv;
        *(float4*)op = ov;
    }
}

// =======================================================================
// launch
// =======================================================================
extern "C" void kernel_launch(void* const* d_in, const int* in_sizes, int n_in,
                              void* d_out, int out_size)
{
    const float* x     = (const float*)d_in[0];
    const int*   mask  = (const int*)  d_in[1];
    const float* wq    = (const float*)d_in[2];
    const float* bq    = (const float*)d_in[3];
    const float* wk    = (const float*)d_in[4];
    const float* bk    = (const float*)d_in[5];
    const float* wv    = (const float*)d_in[6];
    const float* bv    = (const float*)d_in[7];
    const float* wo    = (const float*)d_in[8];
    const float* bo    = (const float*)d_in[9];
    const float* ln1_g = (const float*)d_in[10];
    const float* ln1_b = (const float*)d_in[11];
    const float* ln2_g = (const float*)d_in[12];
    const float* ln2_b = (const float*)d_in[13];
    const float* w1    = (const float*)d_in[14];
    const float* b1    = (const float*)d_in[15];
    const float* w2    = (const float*)d_in[16];
    const float* b2    = (const float*)d_in[17];
    float* out = (float*)d_out;

    float *H, *Q, *K, *V, *CTX, *X2, *FF;
    cudaGetSymbolAddress((void**)&H,   g_H);
    cudaGetSymbolAddress((void**)&Q,   g_Q);
    cudaGetSymbolAddress((void**)&K,   g_K);
    cudaGetSymbolAddress((void**)&V,   g_V);
    cudaGetSymbolAddress((void**)&CTX, g_CTX);
    cudaGetSymbolAddress((void**)&X2,  g_X2);
    cudaGetSymbolAddress((void**)&FF,  g_FF);

    const int attn_smem = 4 * 64 * ATP * (int)sizeof(float);
    cudaFuncSetAttribute(attn_kernel, cudaFuncAttributeMaxDynamicSharedMemorySize, attn_smem);

    dim3 gemm_blk(256);
    dim3 g_dd(DMODEL / BN, MTOK / BM);   // (8, 32)
    dim3 g_ff1(FFDIM / BN, MTOK / BM);   // (32, 32)
    dim3 g_ff2(DMODEL / BN, MTOK / BM);  // (8, 32)

    // residual 1: pre-LN attention
    ln_kernel<<<MTOK, 256>>>(x, ln1_g, ln1_b, H);
    gemm_kernel<<<g_dd, gemm_blk>>>(H, wq, bq, nullptr, Q, MTOK, DMODEL, DMODEL, 0);
    gemm_kernel<<<g_dd, gemm_blk>>>(H, wk, bk, nullptr, K, MTOK, DMODEL, DMODEL, 0);
    gemm_kernel<<<g_dd, gemm_blk>>>(H, wv, bv, nullptr, V, MTOK, DMODEL, DMODEL, 0);
    attn_kernel<<<dim3(SEQ/64, NHEADS, BATCH), 256, attn_smem>>>(Q, K, V, mask, CTX);
    gemm_kernel<<<g_dd, gemm_blk>>>(CTX, wo, bo, x, X2, MTOK, DMODEL, DMODEL, 0);

    // residual 2: pre-LN feed-forward
    ln_kernel<<<MTOK, 256>>>(X2, ln2_g, ln2_b, H);
    gemm_kernel<<<g_ff1, gemm_blk>>>(H, w1, b1, nullptr, FF, MTOK, FFDIM, DMODEL, 1);
    gemm_kernel<<<g_ff2, gemm_blk>>>(FF, w2, b2, X2, out, MTOK, DMODEL, FFDIM, 0);
}

// round 4
// speedup vs baseline: 1.6975x; 1.6975x over previous
#include <cuda_runtime.h>
#include <cuda_bf16.h>
#include <math.h>
#include <stdint.h>

// ---------------- problem constants ----------------
#define BATCH   2
#define SEQ     2048
#define DMODEL  1024
#define NHEADS  16
#define DHEAD   64
#define FFDIM   4096
#define MTOK    (BATCH * SEQ)          // 4096 token rows
#define QKVN    (3 * DMODEL)           // 3072

// ---------------- scratch (device globals; no allocation) ----------------
__device__ float g_H   [MTOK * DMODEL];
__device__ float g_QKV [MTOK * QKVN];
__device__ float g_CTX [MTOK * DMODEL];
__device__ float g_X2  [MTOK * DMODEL];
__device__ float g_FF  [MTOK * FFDIM];
// weights transposed to [N][K] K-major (tf32-rounded fp32 bit patterns)
__device__ float g_Wqkv[QKVN  * DMODEL];
__device__ float g_Wo  [DMODEL * DMODEL];
__device__ float g_W1  [FFDIM * DMODEL];
__device__ float g_W2  [DMODEL * FFDIM];
__device__ float g_Bqkv[QKVN];

__device__ __forceinline__ uint32_t s2u(const void* p) {
    uint32_t a;
    asm("{ .reg .u64 t; cvta.to.shared.u64 t, %1; cvt.u32.u64 %0, t; }" : "=r"(a) : "l"(p));
    return a;
}
__device__ __forceinline__ uint32_t f2tf(float x) {
    uint32_t r; asm("cvt.rna.tf32.f32 %0, %1;" : "=r"(r) : "f"(x)); return r;
}
__device__ __forceinline__ void cp16(uint32_t dst, const void* src) {
    asm volatile("cp.async.cg.shared.global [%0], [%1], 16;" :: "r"(dst), "l"(src));
}
#define CP_COMMIT() asm volatile("cp.async.commit_group;" ::: "memory")
#define CP_WAIT(n)  asm volatile("cp.async.wait_group %0;" :: "n"(n) : "memory")

// =======================================================================
// weight transpose + tf32 round: out[n][k] = tf32(in[k][n]); in is [K][N]
// =======================================================================
__global__ void transpose_tf32(const float* __restrict__ in, float* __restrict__ out,
                               int K, int N)
{
    __shared__ float tile[32][33];
    int n0 = blockIdx.x * 32, k0 = blockIdx.y * 32;
    int tx = threadIdx.x, ty = threadIdx.y;   // 32 x 8
    #pragma unroll
    for (int j = 0; j < 32; j += 8)
        tile[ty + j][tx] = in[(size_t)(k0 + ty + j) * N + n0 + tx];
    __syncthreads();
    #pragma unroll
    for (int j = 0; j < 32; j += 8)
        out[(size_t)(n0 + ty + j) * K + k0 + tx] = __uint_as_float(f2tf(tile[tx][ty + j]));
}

__global__ void concat_bias(const float* __restrict__ a, const float* __restrict__ b,
                            const float* __restrict__ c, float* __restrict__ o)
{
    int i = blockIdx.x * blockDim.x + threadIdx.x;
    if (i < QKVN)
        o[i] = (i < DMODEL) ? a[i] : (i < 2 * DMODEL ? b[i - DMODEL] : c[i - 2 * DMODEL]);
}

// =======================================================================
// LayerNorm
// =======================================================================
__global__ void ln_kernel(const float* __restrict__ x,
                          const float* __restrict__ gamma,
                          const float* __restrict__ beta,
                          float* __restrict__ out)
{
    int row = blockIdx.x;
    int tid = threadIdx.x;
    const float* xr = x + (size_t)row * DMODEL;

    float4 v = *(const float4*)(xr + tid * 4);
    float s  = v.x + v.y + v.z + v.w;
    float sq = v.x*v.x + v.y*v.y + v.z*v.z + v.w*v.w;
    #pragma unroll
    for (int off = 16; off > 0; off >>= 1) {
        s  += __shfl_xor_sync(0xffffffffu, s,  off);
        sq += __shfl_xor_sync(0xffffffffu, sq, off);
    }
    __shared__ float ssum[8], ssq[8];
    int wid = tid >> 5, lane = tid & 31;
    if (lane == 0) { ssum[wid] = s; ssq[wid] = sq; }
    __syncthreads();
    float tot = 0.f, totq = 0.f;
    #pragma unroll
    for (int w = 0; w < 8; w++) { tot += ssum[w]; totq += ssq[w]; }

    const float invN = 1.0f / (float)DMODEL;
    float mean = tot * invN;
    float var  = totq * invN - mean * mean;
    float inv  = rsqrtf(var + 1e-5f);

    float4 g4 = *(const float4*)(gamma + tid * 4);
    float4 b4 = *(const float4*)(beta  + tid * 4);
    float4 o;
    o.x = (v.x - mean) * inv * g4.x + b4.x;
    o.y = (v.y - mean) * inv * g4.y + b4.y;
    o.z = (v.z - mean) * inv * g4.z + b4.z;
    o.w = (v.w - mean) * inv * g4.w + b4.w;
    *(float4*)(out + (size_t)row * DMODEL + tid * 4) = o;
}

// =======================================================================
// tf32 mma.sync GEMM: C[M,N] = A[M,K] @ Wt[N,K]^T + bias (+resid)(relu)
// 128x128x32 tile, 8 warps (2x4), warp tile 64x32, m16n8k8 fragments.
// smem padded to 36 floats/row -> all fragment loads bank-conflict-free.
// =======================================================================
#define BM 128
#define BN 128
#define BK 32
#define PAD 36
#define TILE_FLOATS (128 * PAD)                 // per operand per stage
#define GEMM_SMEM (4 * TILE_FLOATS * 4)         // 2 stages x (A+B) = 73728 B

__device__ __forceinline__ void mma_tf32(float c[4], uint32_t a0, uint32_t a1,
                                         uint32_t a2, uint32_t a3,
                                         uint32_t b0, uint32_t b1)
{
    asm volatile(
        "mma.sync.aligned.m16n8k8.row.col.f32.tf32.tf32.f32 "
        "{%0,%1,%2,%3}, {%4,%5,%6,%7}, {%8,%9}, {%0,%1,%2,%3};"
        : "+f"(c[0]), "+f"(c[1]), "+f"(c[2]), "+f"(c[3])
        : "r"(a0), "r"(a1), "r"(a2), "r"(a3), "r"(b0), "r"(b1));
}

__global__ __launch_bounds__(256, 1)
void gemm_mma(const float* __restrict__ A, const float* __restrict__ Wt,
              const float* __restrict__ bias, const float* __restrict__ resid,
              float* __restrict__ C, int M, int N, int K, int relu)
{
    extern __shared__ float smem[];
    float* As[2] = { smem,                   smem + 2 * TILE_FLOATS };
    float* Bs[2] = { smem + TILE_FLOATS,     smem + 3 * TILE_FLOATS };

    int tid  = threadIdx.x;
    int warp = tid >> 5, lane = tid & 31;
    int wm = warp >> 2;          // 0..1
    int wn = warp & 3;           // 0..3
    int g  = lane >> 2;          // 0..7
    int q  = lane & 3;           // 0..3
    int bm = blockIdx.y * BM;
    int bn = blockIdx.x * BN;

    // staging map: thread -> (row, 4-float col) ; 4 iters cover 128x32
    int s_row = tid >> 3;              // 0..31 (+32*i)
    int s_kq  = (tid & 7) * 4;         // 0,4,...,28

    const int KT = K / BK;

    auto stage = [&](int st, int kt) {
        uint32_t aBase = s2u(As[st]);
        uint32_t bBase = s2u(Bs[st]);
        const float* ag = A  + (size_t)(bm + s_row) * K + kt * BK + s_kq;
        const float* bg = Wt + (size_t)(bn + s_row) * K + kt * BK + s_kq;
        #pragma unroll
        for (int i = 0; i < 4; i++) {
            cp16(aBase + ((s_row + i * 32) * PAD + s_kq) * 4, ag + (size_t)(i * 32) * K);
            cp16(bBase + ((s_row + i * 32) * PAD + s_kq) * 4, bg + (size_t)(i * 32) * K);
        }
    };

    float c[4][4][4];
    #pragma unroll
    for (int mi = 0; mi < 4; mi++)
        #pragma unroll
        for (int ni = 0; ni < 4; ni++)
            #pragma unroll
            for (int r = 0; r < 4; r++) c[mi][ni][r] = 0.f;

    stage(0, 0);
    CP_COMMIT();

    int st = 0;
    for (int kt = 0; kt < KT; kt++) {
        if (kt + 1 < KT) {
            stage(st ^ 1, kt + 1);
            CP_COMMIT();
            CP_WAIT(1);
        } else {
            CP_WAIT(0);
        }
        __syncthreads();

        const float* Af = As[st] + (wm * 64 + g) * PAD + q;
        const float* Bf = Bs[st] + (wn * 32 + g) * PAD + q;
        #pragma unroll
        for (int ks = 0; ks < 4; ks++) {
            uint32_t a[4][4], b[4][2];
            #pragma unroll
            for (int mi = 0; mi < 4; mi++) {
                const float* p = Af + mi * 16 * PAD + ks * 8;
                a[mi][0] = __float_as_uint(p[0]);
                a[mi][1] = __float_as_uint(p[8 * PAD]);
                a[mi][2] = __float_as_uint(p[4]);
                a[mi][3] = __float_as_uint(p[8 * PAD + 4]);
            }
            #pragma unroll
            for (int ni = 0; ni < 4; ni++) {
                const float* p = Bf + ni * 8 * PAD + ks * 8;
                b[ni][0] = __float_as_uint(p[0]);
                b[ni][1] = __float_as_uint(p[4]);
            }
            #pragma unroll
            for (int mi = 0; mi < 4; mi++)
                #pragma unroll
                for (int ni = 0; ni < 4; ni++)
                    mma_tf32(c[mi][ni], a[mi][0], a[mi][1], a[mi][2], a[mi][3],
                             b[ni][0], b[ni][1]);
        }
        __syncthreads();
        st ^= 1;
    }

    // ---- epilogue: c0,c1 -> (row, col..col+1); c2,c3 -> (row+8, ...) ----
    #pragma unroll
    for (int ni = 0; ni < 4; ni++) {
        int col = bn + wn * 32 + ni * 8 + q * 2;
        float2 bv = *(const float2*)(bias + col);
        #pragma unroll
        for (int mi = 0; mi < 4; mi++) {
            int row = bm + wm * 64 + mi * 16 + g;
            #pragma unroll
            for (int half = 0; half < 2; half++) {
                int r = row + half * 8;
                float2 o;
                o.x = c[mi][ni][half * 2 + 0] + bv.x;
                o.y = c[mi][ni][half * 2 + 1] + bv.y;
                if (resid) {
                    float2 rv = *(const float2*)(resid + (size_t)r * N + col);
                    o.x += rv.x; o.y += rv.y;
                }
                if (relu) { o.x = fmaxf(o.x, 0.f); o.y = fmaxf(o.y, 0.f); }
                *(float2*)(C + (size_t)r * N + col) = o;
            }
        }
    }
}

// =======================================================================
// Flash attention (fp32), fused-QKV layout (stride 3072)
// =======================================================================
#define ATP 68
#define NEG_BIG (-1e30f)
#define QKVSTR 3072

__global__ __launch_bounds__(256, 2)
void attn_kernel(const float* __restrict__ QKV, const int* __restrict__ mask,
                 float* __restrict__ O)
{
    extern __shared__ float sm[];
    float* Qs  = sm;
    float* Kst = Qs  + 64 * ATP;
    float* Vs  = Kst + 64 * ATP;
    float* Ps  = Vs  + 64 * ATP;
    __shared__ int msk[64];

    int tid = threadIdx.x;
    int tx = tid & 15;
    int ty = tid >> 4;
    int q0 = blockIdx.x * 64;
    int h  = blockIdx.y;
    int b  = blockIdx.z;

    {
        int r  = tid >> 2;
        int d0 = (tid & 3) * 16;
        const float* qp = QKV + (size_t)(b*SEQ + q0 + r) * QKVSTR + h*DHEAD + d0;
        #pragma unroll
        for (int i = 0; i < 4; i++)
            *(float4*)&Qs[r*ATP + d0 + i*4] = *(const float4*)(qp + i*4);
    }

    float m_i[4] = {NEG_BIG, NEG_BIG, NEG_BIG, NEG_BIG};
    float l_i[4] = {0.f, 0.f, 0.f, 0.f};
    float o[4][4];
    #pragma unroll
    for (int i = 0; i < 4; i++)
        #pragma unroll
        for (int j = 0; j < 4; j++) o[i][j] = 0.f;

    for (int t0 = 0; t0 < SEQ; t0 += 64) {
        {
            int kr = tid >> 2;
            int d0 = (tid & 3) * 16;
            const float* kp = QKV + (size_t)(b*SEQ + t0 + kr) * QKVSTR + DMODEL + h*DHEAD + d0;
            #pragma unroll
            for (int i = 0; i < 4; i++) {
                float4 kv = *(const float4*)(kp + i*4);
                Kst[(d0+i*4+0)*ATP + kr] = kv.x;
                Kst[(d0+i*4+1)*ATP + kr] = kv.y;
                Kst[(d0+i*4+2)*ATP + kr] = kv.z;
                Kst[(d0+i*4+3)*ATP + kr] = kv.w;
            }
            const float* vp = QKV + (size_t)(b*SEQ + t0 + kr) * QKVSTR + 2*DMODEL + h*DHEAD + d0;
            #pragma unroll
            for (int i = 0; i < 4; i++)
                *(float4*)&Vs[kr*ATP + d0 + i*4] = *(const float4*)(vp + i*4);
            if (tid < 64) msk[tid] = mask[b*SEQ + t0 + tid];
        }
        __syncthreads();

        float s[4][4];
        #pragma unroll
        for (int i = 0; i < 4; i++)
            #pragma unroll
            for (int j = 0; j < 4; j++) s[i][j] = 0.f;

        #pragma unroll 8
        for (int d = 0; d < DHEAD; d++) {
            float4 kv = *(const float4*)&Kst[d*ATP + tx*4];
            float q0v = Qs[(ty*4+0)*ATP + d];
            float q1v = Qs[(ty*4+1)*ATP + d];
            float q2v = Qs[(ty*4+2)*ATP + d];
            float q3v = Qs[(ty*4+3)*ATP + d];
            s[0][0] = fmaf(q0v, kv.x, s[0][0]); s[0][1] = fmaf(q0v, kv.y, s[0][1]);
            s[0][2] = fmaf(q0v, kv.z, s[0][2]); s[0][3] = fmaf(q0v, kv.w, s[0][3]);
            s[1][0] = fmaf(q1v, kv.x, s[1][0]); s[1][1] = fmaf(q1v, kv.y, s[1][1]);
            s[1][2] = fmaf(q1v, kv.z, s[1][2]); s[1][3] = fmaf(q1v, kv.w, s[1][3]);
            s[2][0] = fmaf(q2v, kv.x, s[2][0]); s[2][1] = fmaf(q2v, kv.y, s[2][1]);
            s[2][2] = fmaf(q2v, kv.z, s[2][2]); s[2][3] = fmaf(q2v, kv.w, s[2][3]);
            s[3][0] = fmaf(q3v, kv.x, s[3][0]); s[3][1] = fmaf(q3v, kv.y, s[3][1]);
            s[3][2] = fmaf(q3v, kv.z, s[3][2]); s[3][3] = fmaf(q3v, kv.w, s[3][3]);
        }

        const float scale = 0.125f;
        #pragma unroll
        for (int i = 0; i < 4; i++)
            #pragma unroll
            for (int j = 0; j < 4; j++) {
                float sc = s[i][j] * scale;
                if (msk[tx*4 + j] == 0) sc = NEG_BIG;
                s[i][j] = sc;
            }

        #pragma unroll
        for (int i = 0; i < 4; i++) {
            float mn = fmaxf(fmaxf(s[i][0], s[i][1]), fmaxf(s[i][2], s[i][3]));
            #pragma unroll
            for (int off = 8; off > 0; off >>= 1)
                mn = fmaxf(mn, __shfl_xor_sync(0xffffffffu, mn, off));
            mn = fmaxf(mn, m_i[i]);

            float factor = __expf(m_i[i] - mn);
            float rowsum = 0.f;
            #pragma unroll
            for (int j = 0; j < 4; j++) {
                float p = __expf(s[i][j] - mn);
                Ps[(ty*4 + i)*ATP + tx*4 + j] = p;
                rowsum += p;
            }
            #pragma unroll
            for (int off = 8; off > 0; off >>= 1)
                rowsum += __shfl_xor_sync(0xffffffffu, rowsum, off);

            l_i[i] = l_i[i] * factor + rowsum;
            m_i[i] = mn;
            #pragma unroll
            for (int j = 0; j < 4; j++) o[i][j] *= factor;
        }
        __syncthreads();

        #pragma unroll 8
        for (int tk = 0; tk < 64; tk++) {
            float4 vv = *(const float4*)&Vs[tk*ATP + tx*4];
            float p0 = Ps[(ty*4+0)*ATP + tk];
            float p1 = Ps[(ty*4+1)*ATP + tk];
            float p2 = Ps[(ty*4+2)*ATP + tk];
            float p3 = Ps[(ty*4+3)*ATP + tk];
            o[0][0] = fmaf(p0, vv.x, o[0][0]); o[0][1] = fmaf(p0, vv.y, o[0][1]);
            o[0][2] = fmaf(p0, vv.z, o[0][2]); o[0][3] = fmaf(p0, vv.w, o[0][3]);
            o[1][0] = fmaf(p1, vv.x, o[1][0]); o[1][1] = fmaf(p1, vv.y, o[1][1]);
            o[1][2] = fmaf(p1, vv.z, o[1][2]); o[1][3] = fmaf(p1, vv.w, o[1][3]);
            o[2][0] = fmaf(p2, vv.x, o[2][0]); o[2][1] = fmaf(p2, vv.y, o[2][1]);
            o[2][2] = fmaf(p2, vv.z, o[2][2]); o[2][3] = fmaf(p2, vv.w, o[2][3]);
            o[3][0] = fmaf(p3, vv.x, o[3][0]); o[3][1] = fmaf(p3, vv.y, o[3][1]);
            o[3][2] = fmaf(p3, vv.z, o[3][2]); o[3][3] = fmaf(p3, vv.w, o[3][3]);
        }
        __syncthreads();
    }

    #pragma unroll
    for (int i = 0; i < 4; i++) {
        float inv = 1.0f / l_i[i];
        int srow = q0 + ty*4 + i;
        float* op = O + (size_t)(b*SEQ + srow) * DMODEL + h*DHEAD + tx*4;
        float4 ov;
        ov.x = o[i][0]*inv; ov.y = o[i][1]*inv; ov.z = o[i][2]*inv; ov.w = o[i][3]*inv;
        *(float4*)op = ov;
    }
}

// =======================================================================
// launch
// =======================================================================
extern "C" void kernel_launch(void* const* d_in, const int* in_sizes, int n_in,
                              void* d_out, int out_size)
{
    const float* x     = (const float*)d_in[0];
    const int*   mask  = (const int*)  d_in[1];
    const float* wq    = (const float*)d_in[2];
    const float* bq    = (const float*)d_in[3];
    const float* wk    = (const float*)d_in[4];
    const float* bk    = (const float*)d_in[5];
    const float* wv    = (const float*)d_in[6];
    const float* bv    = (const float*)d_in[7];
    const float* wo    = (const float*)d_in[8];
    const float* bo    = (const float*)d_in[9];
    const float* ln1_g = (const float*)d_in[10];
    const float* ln1_b = (const float*)d_in[11];
    const float* ln2_g = (const float*)d_in[12];
    const float* ln2_b = (const float*)d_in[13];
    const float* w1    = (const float*)d_in[14];
    const float* b1    = (const float*)d_in[15];
    const float* w2    = (const float*)d_in[16];
    const float* b2    = (const float*)d_in[17];
    float* out = (float*)d_out;

    float *H, *QKV, *CTX, *X2, *FF, *Wqkv, *Wo, *W1, *W2, *Bqkv;
    cudaGetSymbolAddress((void**)&H,    g_H);
    cudaGetSymbolAddress((void**)&QKV,  g_QKV);
    cudaGetSymbolAddress((void**)&CTX,  g_CTX);
    cudaGetSymbolAddress((void**)&X2,   g_X2);
    cudaGetSymbolAddress((void**)&FF,   g_FF);
    cudaGetSymbolAddress((void**)&Wqkv, g_Wqkv);
    cudaGetSymbolAddress((void**)&Wo,   g_Wo);
    cudaGetSymbolAddress((void**)&W1,   g_W1);
    cudaGetSymbolAddress((void**)&W2,   g_W2);
    cudaGetSymbolAddress((void**)&Bqkv, g_Bqkv);

    cudaFuncSetAttribute(gemm_mma, cudaFuncAttributeMaxDynamicSharedMemorySize, GEMM_SMEM);
    const int attn_smem = 4 * 64 * ATP * (int)sizeof(float);
    cudaFuncSetAttribute(attn_kernel, cudaFuncAttributeMaxDynamicSharedMemorySize, attn_smem);

    dim3 tb(32, 8);
    transpose_tf32<<<dim3(DMODEL/32, DMODEL/32), tb>>>(wq, Wqkv,                   DMODEL, DMODEL);
    transpose_tf32<<<dim3(DMODEL/32, DMODEL/32), tb>>>(wk, Wqkv + DMODEL*DMODEL,   DMODEL, DMODEL);
    transpose_tf32<<<dim3(DMODEL/32, DMODEL/32), tb>>>(wv, Wqkv + 2*DMODEL*DMODEL, DMODEL, DMODEL);
    transpose_tf32<<<dim3(DMODEL/32, DMODEL/32), tb>>>(wo, Wo, DMODEL, DMODEL);
    transpose_tf32<<<dim3(FFDIM/32,  DMODEL/32), tb>>>(w1, W1, DMODEL, FFDIM);
    transpose_tf32<<<dim3(DMODEL/32, FFDIM/32),  tb>>>(w2, W2, FFDIM, DMODEL);
    concat_bias<<<QKVN/256, 256>>>(bq, bk, bv, Bqkv);

    // residual 1: pre-LN attention
    ln_kernel<<<MTOK, 256>>>(x, ln1_g, ln1_b, H);
    gemm_mma<<<dim3(QKVN/BN, MTOK/BM), 256, GEMM_SMEM>>>(H, Wqkv, Bqkv, nullptr, QKV,
                                                         MTOK, QKVN, DMODEL, 0);
    attn_kernel<<<dim3(SEQ/64, NHEADS, BATCH), 256, attn_smem>>>(QKV, mask, CTX);
    gemm_mma<<<dim3(DMODEL/BN, MTOK/BM), 256, GEMM_SMEM>>>(CTX, Wo, bo, x, X2,
                                                           MTOK, DMODEL, DMODEL, 0);

    // residual 2: pre-LN feed-forward
    ln_kernel<<<MTOK, 256>>>(X2, ln2_g, ln2_b, H);
    gemm_mma<<<dim3(FFDIM/BN, MTOK/BM), 256, GEMM_SMEM>>>(H, W1, b1, nullptr, FF,
                                                          MTOK, FFDIM, DMODEL, 1);
    gemm_mma<<<dim3(DMODEL/BN, MTOK/BM), 256, GEMM_SMEM>>>(FF, W2, b2, X2, out,
                                                           MTOK, DMODEL, FFDIM, 0);
}

// round 5
// speedup vs baseline: 2.5224x; 1.4859x over previous
#include <cuda_runtime.h>
#include <cuda_bf16.h>
#include <math.h>
#include <stdint.h>

// ---------------- problem constants ----------------
#define BATCH   2
#define SEQ     2048
#define DMODEL  1024
#define NHEADS  16
#define DHEAD   64
#define FFDIM   4096
#define MTOK    (BATCH * SEQ)          // 4096 token rows
#define QKVN    (3 * DMODEL)           // 3072
#define QKVSTR  3072

// ---------------- scratch (device globals; no allocation) ----------------
__device__ float g_H   [MTOK * DMODEL];
__device__ float g_QKV [MTOK * QKVN];
__device__ float g_CTX [MTOK * DMODEL];
__device__ float g_X2  [MTOK * DMODEL];
__device__ float g_FF  [MTOK * FFDIM];
__device__ float g_Wqkv[QKVN  * DMODEL];
__device__ float g_Wo  [DMODEL * DMODEL];
__device__ float g_W1  [FFDIM * DMODEL];
__device__ float g_W2  [DMODEL * FFDIM];
__device__ float g_Bqkv[QKVN];

__device__ __forceinline__ uint32_t s2u(const void* p) {
    uint32_t a;
    asm("{ .reg .u64 t; cvta.to.shared.u64 t, %1; cvt.u32.u64 %0, t; }" : "=r"(a) : "l"(p));
    return a;
}
__device__ __forceinline__ uint32_t f2tf(float x) {
    uint32_t r; asm("cvt.rna.tf32.f32 %0, %1;" : "=r"(r) : "f"(x)); return r;
}
__device__ __forceinline__ void cp16(uint32_t dst, const void* src) {
    asm volatile("cp.async.cg.shared.global [%0], [%1], 16;" :: "r"(dst), "l"(src));
}
#define CP_COMMIT() asm volatile("cp.async.commit_group;" ::: "memory")
#define CP_WAIT(n)  asm volatile("cp.async.wait_group %0;" :: "n"(n) : "memory")

__device__ __forceinline__ void mma_tf32(float c[4], uint32_t a0, uint32_t a1,
                                         uint32_t a2, uint32_t a3,
                                         uint32_t b0, uint32_t b1)
{
    asm volatile(
        "mma.sync.aligned.m16n8k8.row.col.f32.tf32.tf32.f32 "
        "{%0,%1,%2,%3}, {%4,%5,%6,%7}, {%8,%9}, {%0,%1,%2,%3};"
        : "+f"(c[0]), "+f"(c[1]), "+f"(c[2]), "+f"(c[3])
        : "r"(a0), "r"(a1), "r"(a2), "r"(a3), "r"(b0), "r"(b1));
}

// =======================================================================
// weight transpose + tf32 round
// =======================================================================
__global__ void transpose_tf32(const float* __restrict__ in, float* __restrict__ out,
                               int K, int N)
{
    __shared__ float tile[32][33];
    int n0 = blockIdx.x * 32, k0 = blockIdx.y * 32;
    int tx = threadIdx.x, ty = threadIdx.y;
    #pragma unroll
    for (int j = 0; j < 32; j += 8)
        tile[ty + j][tx] = in[(size_t)(k0 + ty + j) * N + n0 + tx];
    __syncthreads();
    #pragma unroll
    for (int j = 0; j < 32; j += 8)
        out[(size_t)(n0 + ty + j) * K + k0 + tx] = __uint_as_float(f2tf(tile[tx][ty + j]));
}

__global__ void concat_bias(const float* __restrict__ a, const float* __restrict__ b,
                            const float* __restrict__ c, float* __restrict__ o)
{
    int i = blockIdx.x * blockDim.x + threadIdx.x;
    if (i < QKVN)
        o[i] = (i < DMODEL) ? a[i] : (i < 2 * DMODEL ? b[i - DMODEL] : c[i - 2 * DMODEL]);
}

// =======================================================================
// LayerNorm
// =======================================================================
__global__ void ln_kernel(const float* __restrict__ x,
                          const float* __restrict__ gamma,
                          const float* __restrict__ beta,
                          float* __restrict__ out)
{
    int row = blockIdx.x;
    int tid = threadIdx.x;
    const float* xr = x + (size_t)row * DMODEL;

    float4 v = *(const float4*)(xr + tid * 4);
    float s  = v.x + v.y + v.z + v.w;
    float sq = v.x*v.x + v.y*v.y + v.z*v.z + v.w*v.w;
    #pragma unroll
    for (int off = 16; off > 0; off >>= 1) {
        s  += __shfl_xor_sync(0xffffffffu, s,  off);
        sq += __shfl_xor_sync(0xffffffffu, sq, off);
    }
    __shared__ float ssum[8], ssq[8];
    int wid = tid >> 5, lane = tid & 31;
    if (lane == 0) { ssum[wid] = s; ssq[wid] = sq; }
    __syncthreads();
    float tot = 0.f, totq = 0.f;
    #pragma unroll
    for (int w = 0; w < 8; w++) { tot += ssum[w]; totq += ssq[w]; }

    const float invN = 1.0f / (float)DMODEL;
    float mean = tot * invN;
    float var  = totq * invN - mean * mean;
    float inv  = rsqrtf(var + 1e-5f);

    float4 g4 = *(const float4*)(gamma + tid * 4);
    float4 b4 = *(const float4*)(beta  + tid * 4);
    float4 o;
    o.x = (v.x - mean) * inv * g4.x + b4.x;
    o.y = (v.y - mean) * inv * g4.y + b4.y;
    o.z = (v.z - mean) * inv * g4.z + b4.z;
    o.w = (v.w - mean) * inv * g4.w + b4.w;
    *(float4*)(out + (size_t)row * DMODEL + tid * 4) = o;
}

// =======================================================================
// tf32 mma.sync GEMM (identical to round 4 — passing)
// =======================================================================
#define BM 128
#define BN 128
#define BK 32
#define PAD 36
#define TILE_FLOATS (128 * PAD)
#define GEMM_SMEM (4 * TILE_FLOATS * 4)

__global__ __launch_bounds__(256, 1)
void gemm_mma(const float* __restrict__ A, const float* __restrict__ Wt,
              const float* __restrict__ bias, const float* __restrict__ resid,
              float* __restrict__ C, int M, int N, int K, int relu)
{
    extern __shared__ float smem[];
    float* As[2] = { smem,                   smem + 2 * TILE_FLOATS };
    float* Bs[2] = { smem + TILE_FLOATS,     smem + 3 * TILE_FLOATS };

    int tid  = threadIdx.x;
    int warp = tid >> 5, lane = tid & 31;
    int wm = warp >> 2;
    int wn = warp & 3;
    int g  = lane >> 2;
    int q  = lane & 3;
    int bm = blockIdx.y * BM;
    int bn = blockIdx.x * BN;

    int s_row = tid >> 3;
    int s_kq  = (tid & 7) * 4;

    const int KT = K / BK;

    auto stage = [&](int st, int kt) {
        uint32_t aBase = s2u(As[st]);
        uint32_t bBase = s2u(Bs[st]);
        const float* ag = A  + (size_t)(bm + s_row) * K + kt * BK + s_kq;
        const float* bg = Wt + (size_t)(bn + s_row) * K + kt * BK + s_kq;
        #pragma unroll
        for (int i = 0; i < 4; i++) {
            cp16(aBase + ((s_row + i * 32) * PAD + s_kq) * 4, ag + (size_t)(i * 32) * K);
            cp16(bBase + ((s_row + i * 32) * PAD + s_kq) * 4, bg + (size_t)(i * 32) * K);
        }
    };

    float c[4][4][4];
    #pragma unroll
    for (int mi = 0; mi < 4; mi++)
        #pragma unroll
        for (int ni = 0; ni < 4; ni++)
            #pragma unroll
            for (int r = 0; r < 4; r++) c[mi][ni][r] = 0.f;

    stage(0, 0);
    CP_COMMIT();

    int st = 0;
    for (int kt = 0; kt < KT; kt++) {
        if (kt + 1 < KT) {
            stage(st ^ 1, kt + 1);
            CP_COMMIT();
            CP_WAIT(1);
        } else {
            CP_WAIT(0);
        }
        __syncthreads();

        const float* Af = As[st] + (wm * 64 + g) * PAD + q;
        const float* Bf = Bs[st] + (wn * 32 + g) * PAD + q;
        #pragma unroll
        for (int ks = 0; ks < 4; ks++) {
            uint32_t a[4][4], b[4][2];
            #pragma unroll
            for (int mi = 0; mi < 4; mi++) {
                const float* p = Af + mi * 16 * PAD + ks * 8;
                a[mi][0] = __float_as_uint(p[0]);
                a[mi][1] = __float_as_uint(p[8 * PAD]);
                a[mi][2] = __float_as_uint(p[4]);
                a[mi][3] = __float_as_uint(p[8 * PAD + 4]);
            }
            #pragma unroll
            for (int ni = 0; ni < 4; ni++) {
                const float* p = Bf + ni * 8 * PAD + ks * 8;
                b[ni][0] = __float_as_uint(p[0]);
                b[ni][1] = __float_as_uint(p[4]);
            }
            #pragma unroll
            for (int mi = 0; mi < 4; mi++)
                #pragma unroll
                for (int ni = 0; ni < 4; ni++)
                    mma_tf32(c[mi][ni], a[mi][0], a[mi][1], a[mi][2], a[mi][3],
                             b[ni][0], b[ni][1]);
        }
        __syncthreads();
        st ^= 1;
    }

    #pragma unroll
    for (int ni = 0; ni < 4; ni++) {
        int col = bn + wn * 32 + ni * 8 + q * 2;
        float2 bv = *(const float2*)(bias + col);
        #pragma unroll
        for (int mi = 0; mi < 4; mi++) {
            int row = bm + wm * 64 + mi * 16 + g;
            #pragma unroll
            for (int half = 0; half < 2; half++) {
                int r = row + half * 8;
                float2 o;
                o.x = c[mi][ni][half * 2 + 0] + bv.x;
                o.y = c[mi][ni][half * 2 + 1] + bv.y;
                if (resid) {
                    float2 rv = *(const float2*)(resid + (size_t)r * N + col);
                    o.x += rv.x; o.y += rv.y;
                }
                if (relu) { o.x = fmaxf(o.x, 0.f); o.y = fmaxf(o.y, 0.f); }
                *(float2*)(C + (size_t)r * N + col) = o;
            }
        }
    }
}

// =======================================================================
// tf32 tensor-core flash attention
// block = 128 q-rows x one (b,h); 8 warps x 16 rows; key tiles of 64.
// smem: Qs[128][68] (tf32*scale), Ks[64][68] (raw fp32 -> tf32 trunc in mma),
//       Vt[64][68] (transposed, tf32), msk[64].
// Fragment layouts identical to gemm_mma (validated).
// =======================================================================
#define APAD 68
#define NEG_BIG (-1e30f)
#define ATTN_SMEM ((128 + 64 + 64) * APAD * 4 + 64 * 4)

__global__ __launch_bounds__(256, 1)
void attn_mma(const float* __restrict__ QKV, const int* __restrict__ mask,
              float* __restrict__ O)
{
    extern __shared__ float sm[];
    float* Qs = sm;                        // [128][APAD]
    float* Ks = Qs + 128 * APAD;           // [64][APAD]  (key-major, d minor)
    float* Vt = Ks + 64 * APAD;            // [64][APAD]  (d-major, key minor)
    int*   msk = (int*)(Vt + 64 * APAD);   // [64]

    int tid  = threadIdx.x;
    int warp = tid >> 5, lane = tid & 31;
    int g = lane >> 2, q = lane & 3;
    int row0 = warp * 16;
    int q0 = blockIdx.x * 128;
    int h  = blockIdx.y;
    int b  = blockIdx.z;

    // ---- stage Q (scale folded; 0.125 is exact so rounding commutes) ----
    {
        int r  = tid >> 1;
        int c0 = (tid & 1) * 32;
        const float* qp = QKV + (size_t)(b*SEQ + q0 + r) * QKVSTR + h*DHEAD + c0;
        float* qd = &Qs[r * APAD + c0];
        #pragma unroll
        for (int i = 0; i < 8; i++) {
            float4 v = *(const float4*)(qp + i * 4);
            qd[i*4+0] = __uint_as_float(f2tf(v.x * 0.125f));
            qd[i*4+1] = __uint_as_float(f2tf(v.y * 0.125f));
            qd[i*4+2] = __uint_as_float(f2tf(v.z * 0.125f));
            qd[i*4+3] = __uint_as_float(f2tf(v.w * 0.125f));
        }
    }

    float m_r[2] = {NEG_BIG, NEG_BIG};
    float l_r[2] = {0.f, 0.f};
    float o[8][4];
    #pragma unroll
    for (int nv = 0; nv < 8; nv++)
        #pragma unroll
        for (int r = 0; r < 4; r++) o[nv][r] = 0.f;

    int base = lane & ~3;   // quad base lane

    for (int t0 = 0; t0 < SEQ; t0 += 64) {
        // ---- stage K (cp.async, raw fp32; mma truncates to tf32) ----
        {
            int key = tid >> 2;
            int cb  = (tid & 3) * 16;
            const float* kp = QKV + (size_t)(b*SEQ + t0 + key) * QKVSTR + DMODEL + h*DHEAD;
            uint32_t kd = s2u(&Ks[key * APAD]);
            #pragma unroll
            for (int i = 0; i < 4; i++)
                cp16(kd + (cb + i * 4) * 4, kp + cb + i * 4);
        }
        CP_COMMIT();
        // ---- stage V transposed (ldg + cvt + scalar sts) ----
        {
            int key = tid >> 2;
            int db  = (tid & 3) * 16;
            const float* vp = QKV + (size_t)(b*SEQ + t0 + key) * QKVSTR + 2*DMODEL + h*DHEAD + db;
            #pragma unroll
            for (int i = 0; i < 4; i++) {
                float4 v = *(const float4*)(vp + i * 4);
                Vt[(db + i*4 + 0) * APAD + key] = __uint_as_float(f2tf(v.x));
                Vt[(db + i*4 + 1) * APAD + key] = __uint_as_float(f2tf(v.y));
                Vt[(db + i*4 + 2) * APAD + key] = __uint_as_float(f2tf(v.z));
                Vt[(db + i*4 + 3) * APAD + key] = __uint_as_float(f2tf(v.w));
            }
        }
        if (tid < 64) msk[tid] = mask[b*SEQ + t0 + tid];
        CP_WAIT(0);
        __syncthreads();

        // ---- S = Q @ K^T (c-frags: rows row0+g/+8, cols nj*8+2q/+1) ----
        float sc[8][4];
        #pragma unroll
        for (int nj = 0; nj < 8; nj++)
            #pragma unroll
            for (int r = 0; r < 4; r++) sc[nj][r] = 0.f;

        #pragma unroll
        for (int ks = 0; ks < 8; ks++) {
            const float* ap = &Qs[(row0 + g) * APAD + ks * 8 + q];
            uint32_t a0 = __float_as_uint(ap[0]);
            uint32_t a1 = __float_as_uint(ap[8 * APAD]);
            uint32_t a2 = __float_as_uint(ap[4]);
            uint32_t a3 = __float_as_uint(ap[8 * APAD + 4]);
            #pragma unroll
            for (int nj = 0; nj < 8; nj++) {
                const float* bp = &Ks[(nj * 8 + g) * APAD + ks * 8 + q];
                mma_tf32(sc[nj], a0, a1, a2, a3,
                         __float_as_uint(bp[0]), __float_as_uint(bp[4]));
            }
        }

        // ---- mask ----
        #pragma unroll
        for (int nj = 0; nj < 8; nj++) {
            int c0 = nj * 8 + 2 * q;
            if (msk[c0]     == 0) { sc[nj][0] = NEG_BIG; sc[nj][2] = NEG_BIG; }
            if (msk[c0 + 1] == 0) { sc[nj][1] = NEG_BIG; sc[nj][3] = NEG_BIG; }
        }

        // ---- online softmax (rows r0=row0+g, r1=row0+g+8) ----
        float mx0 = NEG_BIG, mx1 = NEG_BIG;
        #pragma unroll
        for (int nj = 0; nj < 8; nj++) {
            mx0 = fmaxf(mx0, fmaxf(sc[nj][0], sc[nj][1]));
            mx1 = fmaxf(mx1, fmaxf(sc[nj][2], sc[nj][3]));
        }
        mx0 = fmaxf(mx0, __shfl_xor_sync(0xffffffffu, mx0, 1));
        mx0 = fmaxf(mx0, __shfl_xor_sync(0xffffffffu, mx0, 2));
        mx1 = fmaxf(mx1, __shfl_xor_sync(0xffffffffu, mx1, 1));
        mx1 = fmaxf(mx1, __shfl_xor_sync(0xffffffffu, mx1, 2));
        float mn0 = fmaxf(m_r[0], mx0);
        float mn1 = fmaxf(m_r[1], mx1);
        float fac0 = __expf(m_r[0] - mn0);
        float fac1 = __expf(m_r[1] - mn1);

        float sum0 = 0.f, sum1 = 0.f;
        #pragma unroll
        for (int nj = 0; nj < 8; nj++) {
            sc[nj][0] = __expf(sc[nj][0] - mn0);
            sc[nj][1] = __expf(sc[nj][1] - mn0);
            sc[nj][2] = __expf(sc[nj][2] - mn1);
            sc[nj][3] = __expf(sc[nj][3] - mn1);
            sum0 += sc[nj][0] + sc[nj][1];
            sum1 += sc[nj][2] + sc[nj][3];
        }
        sum0 += __shfl_xor_sync(0xffffffffu, sum0, 1);
        sum0 += __shfl_xor_sync(0xffffffffu, sum0, 2);
        sum1 += __shfl_xor_sync(0xffffffffu, sum1, 1);
        sum1 += __shfl_xor_sync(0xffffffffu, sum1, 2);

        l_r[0] = l_r[0] * fac0 + sum0;  m_r[0] = mn0;
        l_r[1] = l_r[1] * fac1 + sum1;  m_r[1] = mn1;

        #pragma unroll
        for (int nv = 0; nv < 8; nv++) {
            o[nv][0] *= fac0; o[nv][1] *= fac0;
            o[nv][2] *= fac1; o[nv][3] *= fac1;
        }

        // ---- O += P @ V : C-frag -> A-frag via quad shuffles ----
        #pragma unroll
        for (int ks = 0; ks < 8; ks++) {
            int sl = base | (q >> 1);
            int sh = base | ((q >> 1) + 2);
            float vl0 = __shfl_sync(0xffffffffu, sc[ks][0], sl);
            float vh0 = __shfl_sync(0xffffffffu, sc[ks][1], sl);
            float ul0 = __shfl_sync(0xffffffffu, sc[ks][0], sh);
            float uh0 = __shfl_sync(0xffffffffu, sc[ks][1], sh);
            float vl1 = __shfl_sync(0xffffffffu, sc[ks][2], sl);
            float vh1 = __shfl_sync(0xffffffffu, sc[ks][3], sl);
            float ul1 = __shfl_sync(0xffffffffu, sc[ks][2], sh);
            float uh1 = __shfl_sync(0xffffffffu, sc[ks][3], sh);
            uint32_t A0 = f2tf((q & 1) ? vh0 : vl0);
            uint32_t A2 = f2tf((q & 1) ? uh0 : ul0);
            uint32_t A1 = f2tf((q & 1) ? vh1 : vl1);
            uint32_t A3 = f2tf((q & 1) ? uh1 : ul1);
            #pragma unroll
            for (int nv = 0; nv < 8; nv++) {
                const float* bp = &Vt[(nv * 8 + g) * APAD + ks * 8 + q];
                mma_tf32(o[nv], A0, A1, A2, A3,
                         __float_as_uint(bp[0]), __float_as_uint(bp[4]));
            }
        }
        __syncthreads();
    }

    // ---- write ctx ----
    float inv0 = 1.0f / l_r[0];
    float inv1 = 1.0f / l_r[1];
    int r0 = q0 + row0 + g;
    int r1 = r0 + 8;
    #pragma unroll
    for (int nv = 0; nv < 8; nv++) {
        int col = h * DHEAD + nv * 8 + 2 * q;
        float2 w0, w1;
        w0.x = o[nv][0] * inv0; w0.y = o[nv][1] * inv0;
        w1.x = o[nv][2] * inv1; w1.y = o[nv][3] * inv1;
        *(float2*)(O + (size_t)(b*SEQ + r0) * DMODEL + col) = w0;
        *(float2*)(O + (size_t)(b*SEQ + r1) * DMODEL + col) = w1;
    }
}

// =======================================================================
// launch
// =======================================================================
extern "C" void kernel_launch(void* const* d_in, const int* in_sizes, int n_in,
                              void* d_out, int out_size)
{
    const float* x     = (const float*)d_in[0];
    const int*   mask  = (const int*)  d_in[1];
    const float* wq    = (const float*)d_in[2];
    const float* bq    = (const float*)d_in[3];
    const float* wk    = (const float*)d_in[4];
    const float* bk    = (const float*)d_in[5];
    const float* wv    = (const float*)d_in[6];
    const float* bv    = (const float*)d_in[7];
    const float* wo    = (const float*)d_in[8];
    const float* bo    = (const float*)d_in[9];
    const float* ln1_g = (const float*)d_in[10];
    const float* ln1_b = (const float*)d_in[11];
    const float* ln2_g = (const float*)d_in[12];
    const float* ln2_b = (const float*)d_in[13];
    const float* w1    = (const float*)d_in[14];
    const float* b1    = (const float*)d_in[15];
    const float* w2    = (const float*)d_in[16];
    const float* b2    = (const float*)d_in[17];
    float* out = (float*)d_out;

    float *H, *QKV, *CTX, *X2, *FF, *Wqkv, *Wo, *W1, *W2, *Bqkv;
    cudaGetSymbolAddress((void**)&H,    g_H);
    cudaGetSymbolAddress((void**)&QKV,  g_QKV);
    cudaGetSymbolAddress((void**)&CTX,  g_CTX);
    cudaGetSymbolAddress((void**)&X2,   g_X2);
    cudaGetSymbolAddress((void**)&FF,   g_FF);
    cudaGetSymbolAddress((void**)&Wqkv, g_Wqkv);
    cudaGetSymbolAddress((void**)&Wo,   g_Wo);
    cudaGetSymbolAddress((void**)&W1,   g_W1);
    cudaGetSymbolAddress((void**)&W2,   g_W2);
    cudaGetSymbolAddress((void**)&Bqkv, g_Bqkv);

    cudaFuncSetAttribute(gemm_mma, cudaFuncAttributeMaxDynamicSharedMemorySize, GEMM_SMEM);
    cudaFuncSetAttribute(attn_mma, cudaFuncAttributeMaxDynamicSharedMemorySize, ATTN_SMEM);

    dim3 tb(32, 8);
    transpose_tf32<<<dim3(DMODEL/32, DMODEL/32), tb>>>(wq, Wqkv,                   DMODEL, DMODEL);
    transpose_tf32<<<dim3(DMODEL/32, DMODEL/32), tb>>>(wk, Wqkv + DMODEL*DMODEL,   DMODEL, DMODEL);
    transpose_tf32<<<dim3(DMODEL/32, DMODEL/32), tb>>>(wv, Wqkv + 2*DMODEL*DMODEL, DMODEL, DMODEL);
    transpose_tf32<<<dim3(DMODEL/32, DMODEL/32), tb>>>(wo, Wo, DMODEL, DMODEL);
    transpose_tf32<<<dim3(FFDIM/32,  DMODEL/32), tb>>>(w1, W1, DMODEL, FFDIM);
    transpose_tf32<<<dim3(DMODEL/32, FFDIM/32),  tb>>>(w2, W2, FFDIM, DMODEL);
    concat_bias<<<QKVN/256, 256>>>(bq, bk, bv, Bqkv);

    // residual 1: pre-LN attention
    ln_kernel<<<MTOK, 256>>>(x, ln1_g, ln1_b, H);
    gemm_mma<<<dim3(QKVN/BN, MTOK/BM), 256, GEMM_SMEM>>>(H, Wqkv, Bqkv, nullptr, QKV,
                                                         MTOK, QKVN, DMODEL, 0);
    attn_mma<<<dim3(SEQ/128, NHEADS, BATCH), 256, ATTN_SMEM>>>(QKV, mask, CTX);
    gemm_mma<<<dim3(DMODEL/BN, MTOK/BM), 256, GEMM_SMEM>>>(CTX, Wo, bo, x, X2,
                                                           MTOK, DMODEL, DMODEL, 0);

    // residual 2: pre-LN feed-forward
    ln_kernel<<<MTOK, 256>>>(X2, ln2_g, ln2_b, H);
    gemm_mma<<<dim3(FFDIM/BN, MTOK/BM), 256, GEMM_SMEM>>>(H, W1, b1, nullptr, FF,
                                                          MTOK, FFDIM, DMODEL, 1);
    gemm_mma<<<dim3(DMODEL/BN, MTOK/BM), 256, GEMM_SMEM>>>(FF, W2, b2, X2, out,
                                                           MTOK, DMODEL, FFDIM, 0);
}

// round 7
// speedup vs baseline: 2.8713x; 1.1383x over previous
#include <cuda_runtime.h>
#include <cuda_bf16.h>
#include <math.h>
#include <stdint.h>

// ---------------- problem constants ----------------
#define BATCH   2
#define SEQ     2048
#define DMODEL  1024
#define NHEADS  16
#define DHEAD   64
#define FFDIM   4096
#define MTOK    (BATCH * SEQ)          // 4096 token rows
#define QKVN    (3 * DMODEL)           // 3072
#define QKVSTR  3072

// ---------------- scratch (device globals; no allocation) ----------------
__device__ float g_H   [MTOK * DMODEL];
__device__ float g_QKV [MTOK * QKVN];
__device__ float g_CTX [MTOK * DMODEL];
__device__ float g_X2  [MTOK * DMODEL];
__device__ float g_FF  [MTOK * FFDIM];
__device__ float g_Wqkv[QKVN  * DMODEL];
__device__ float g_Wo  [DMODEL * DMODEL];
__device__ float g_W1  [FFDIM * DMODEL];
__device__ float g_W2  [DMODEL * FFDIM];
__device__ float g_Bqkv[QKVN];

__device__ __forceinline__ uint32_t s2u(const void* p) {
    uint32_t a;
    asm("{ .reg .u64 t; cvta.to.shared.u64 t, %1; cvt.u32.u64 %0, t; }" : "=r"(a) : "l"(p));
    return a;
}
__device__ __forceinline__ uint32_t f2tf(float x) {
    uint32_t r; asm("cvt.rna.tf32.f32 %0, %1;" : "=r"(r) : "f"(x)); return r;
}
__device__ __forceinline__ void cp16(uint32_t dst, const void* src) {
    asm volatile("cp.async.cg.shared.global [%0], [%1], 16;" :: "r"(dst), "l"(src));
}
#define CP_COMMIT() asm volatile("cp.async.commit_group;" ::: "memory")
#define CP_WAIT(n)  asm volatile("cp.async.wait_group %0;" :: "n"(n) : "memory")

__device__ __forceinline__ void mma_tf32(float c[4], uint32_t a0, uint32_t a1,
                                         uint32_t a2, uint32_t a3,
                                         uint32_t b0, uint32_t b1)
{
    asm volatile(
        "mma.sync.aligned.m16n8k8.row.col.f32.tf32.tf32.f32 "
        "{%0,%1,%2,%3}, {%4,%5,%6,%7}, {%8,%9}, {%0,%1,%2,%3};"
        : "+f"(c[0]), "+f"(c[1]), "+f"(c[2]), "+f"(c[3])
        : "r"(a0), "r"(a1), "r"(a2), "r"(a3), "r"(b0), "r"(b1));
}

// =======================================================================
// weight transpose + tf32 round
// =======================================================================
__global__ void transpose_tf32(const float* __restrict__ in, float* __restrict__ out,
                               int K, int N)
{
    __shared__ float tile[32][33];
    int n0 = blockIdx.x * 32, k0 = blockIdx.y * 32;
    int tx = threadIdx.x, ty = threadIdx.y;
    #pragma unroll
    for (int j = 0; j < 32; j += 8)
        tile[ty + j][tx] = in[(size_t)(k0 + ty + j) * N + n0 + tx];
    __syncthreads();
    #pragma unroll
    for (int j = 0; j < 32; j += 8)
        out[(size_t)(n0 + ty + j) * K + k0 + tx] = __uint_as_float(f2tf(tile[tx][ty + j]));
}

__global__ void concat_bias(const float* __restrict__ a, const float* __restrict__ b,
                            const float* __restrict__ c, float* __restrict__ o)
{
    int i = blockIdx.x * blockDim.x + threadIdx.x;
    if (i < QKVN)
        o[i] = (i < DMODEL) ? a[i] : (i < 2 * DMODEL ? b[i - DMODEL] : c[i - 2 * DMODEL]);
}

// =======================================================================
// LayerNorm
// =======================================================================
__global__ void ln_kernel(const float* __restrict__ x,
                          const float* __restrict__ gamma,
                          const float* __restrict__ beta,
                          float* __restrict__ out)
{
    int row = blockIdx.x;
    int tid = threadIdx.x;
    const float* xr = x + (size_t)row * DMODEL;

    float4 v = *(const float4*)(xr + tid * 4);
    float s  = v.x + v.y + v.z + v.w;
    float sq = v.x*v.x + v.y*v.y + v.z*v.z + v.w*v.w;
    #pragma unroll
    for (int off = 16; off > 0; off >>= 1) {
        s  += __shfl_xor_sync(0xffffffffu, s,  off);
        sq += __shfl_xor_sync(0xffffffffu, sq, off);
    }
    __shared__ float ssum[8], ssq[8];
    int wid = tid >> 5, lane = tid & 31;
    if (lane == 0) { ssum[wid] = s; ssq[wid] = sq; }
    __syncthreads();
    float tot = 0.f, totq = 0.f;
    #pragma unroll
    for (int w = 0; w < 8; w++) { tot += ssum[w]; totq += ssq[w]; }

    const float invN = 1.0f / (float)DMODEL;
    float mean = tot * invN;
    float var  = totq * invN - mean * mean;
    float inv  = rsqrtf(var + 1e-5f);

    float4 g4 = *(const float4*)(gamma + tid * 4);
    float4 b4 = *(const float4*)(beta  + tid * 4);
    float4 o;
    o.x = (v.x - mean) * inv * g4.x + b4.x;
    o.y = (v.y - mean) * inv * g4.y + b4.y;
    o.z = (v.z - mean) * inv * g4.z + b4.z;
    o.w = (v.w - mean) * inv * g4.w + b4.w;
    *(float4*)(out + (size_t)row * DMODEL + tid * 4) = o;
}

// =======================================================================
// tf32 mma.sync GEMM: C[M,N] = A[M,K] @ Wt[N,K]^T + bias (+resid)(relu)
// block tile 128x256, BK=32; 8 warps 2x4; warp tile 64x64 (mi=4, ni=8).
// PAD=36 -> all fragment loads bank-conflict-free (bank = 4g+q).
// =======================================================================
#define BM 128
#define BN 256
#define BK 32
#define PAD 36
#define A_FLOATS (128 * PAD)
#define B_FLOATS (256 * PAD)
#define STG_FLOATS (A_FLOATS + B_FLOATS)
#define GEMM_SMEM (2 * STG_FLOATS * 4)          // 110592 B

__global__ __launch_bounds__(256, 1)
void gemm_mma(const float* __restrict__ A, const float* __restrict__ Wt,
              const float* __restrict__ bias, const float* __restrict__ resid,
              float* __restrict__ C, int M, int N, int K, int relu)
{
    extern __shared__ float smem[];
    float* As[2] = { smem,            smem + STG_FLOATS };
    float* Bs[2] = { smem + A_FLOATS, smem + STG_FLOATS + A_FLOATS };

    int tid  = threadIdx.x;
    int warp = tid >> 5, lane = tid & 31;
    int wm = warp >> 2;          // 0..1  -> 64-row group
    int wn = warp & 3;           // 0..3  -> 64-col group
    int g  = lane >> 2;          // 0..7
    int q  = lane & 3;           // 0..3
    int bm = blockIdx.y * BM;
    int bn = blockIdx.x * BN;

    // staging map: thread -> (row, 4-float col)
    int s_row = tid >> 3;              // 0..31 (+32*i)
    int s_kq  = (tid & 7) * 4;         // 0,4,...,28

    const int KT = K / BK;

    auto stage = [&](int st, int kt) {
        uint32_t aBase = s2u(As[st]);
        uint32_t bBase = s2u(Bs[st]);
        const float* ag = A  + (size_t)(bm + s_row) * K + kt * BK + s_kq;
        const float* bg = Wt + (size_t)(bn + s_row) * K + kt * BK + s_kq;
        #pragma unroll
        for (int i = 0; i < 4; i++)   // A: 128 rows
            cp16(aBase + ((s_row + i * 32) * PAD + s_kq) * 4, ag + (size_t)(i * 32) * K);
        #pragma unroll
        for (int i = 0; i < 8; i++)   // B: 256 rows
            cp16(bBase + ((s_row + i * 32) * PAD + s_kq) * 4, bg + (size_t)(i * 32) * K);
    };

    float c[4][8][4];
    #pragma unroll
    for (int mi = 0; mi < 4; mi++)
        #pragma unroll
        for (int ni = 0; ni < 8; ni++)
            #pragma unroll
            for (int r = 0; r < 4; r++) c[mi][ni][r] = 0.f;

    stage(0, 0);
    CP_COMMIT();

    int st = 0;
    for (int kt = 0; kt < KT; kt++) {
        if (kt + 1 < KT) {
            stage(st ^ 1, kt + 1);
            CP_COMMIT();
            CP_WAIT(1);
        } else {
            CP_WAIT(0);
        }
        __syncthreads();

        const float* Af = As[st] + (wm * 64 + g) * PAD + q;
        const float* Bf = Bs[st] + (wn * 64 + g) * PAD + q;
        #pragma unroll
        for (int ks = 0; ks < 4; ks++) {
            uint32_t a[4][4], b[8][2];
            #pragma unroll
            for (int mi = 0; mi < 4; mi++) {
                const float* p = Af + mi * 16 * PAD + ks * 8;
                a[mi][0] = __float_as_uint(p[0]);
                a[mi][1] = __float_as_uint(p[8 * PAD]);
                a[mi][2] = __float_as_uint(p[4]);
                a[mi][3] = __float_as_uint(p[8 * PAD + 4]);
            }
            #pragma unroll
            for (int ni = 0; ni < 8; ni++) {
                const float* p = Bf + ni * 8 * PAD + ks * 8;
                b[ni][0] = __float_as_uint(p[0]);
                b[ni][1] = __float_as_uint(p[4]);
            }
            #pragma unroll
            for (int mi = 0; mi < 4; mi++)
                #pragma unroll
                for (int ni = 0; ni < 8; ni++)
                    mma_tf32(c[mi][ni], a[mi][0], a[mi][1], a[mi][2], a[mi][3],
                             b[ni][0], b[ni][1]);
        }
        __syncthreads();
        st ^= 1;
    }

    // ---- epilogue ----
    #pragma unroll
    for (int ni = 0; ni < 8; ni++) {
        int col = bn + wn * 64 + ni * 8 + q * 2;
        float2 bv = *(const float2*)(bias + col);
        #pragma unroll
        for (int mi = 0; mi < 4; mi++) {
            int row = bm + wm * 64 + mi * 16 + g;
            #pragma unroll
            for (int half = 0; half < 2; half++) {
                int r = row + half * 8;
                float2 o;
                o.x = c[mi][ni][half * 2 + 0] + bv.x;
                o.y = c[mi][ni][half * 2 + 1] + bv.y;
                if (resid) {
                    float2 rv = *(const float2*)(resid + (size_t)r * N + col);
                    o.x += rv.x; o.y += rv.y;
                }
                if (relu) { o.x = fmaxf(o.x, 0.f); o.y = fmaxf(o.y, 0.f); }
                *(float2*)(C + (size_t)r * N + col) = o;
            }
        }
    }
}

// =======================================================================
// tf32 tensor-core flash attention (identical to round 5 — passing)
// =======================================================================
#define APAD 68
#define NEG_BIG (-1e30f)
#define ATTN_SMEM ((128 + 64 + 64) * APAD * 4 + 64 * 4)

__global__ __launch_bounds__(256, 1)
void attn_mma(const float* __restrict__ QKV, const int* __restrict__ mask,
              float* __restrict__ O)
{
    extern __shared__ float sm[];
    float* Qs = sm;                        // [128][APAD]
    float* Ks = Qs + 128 * APAD;           // [64][APAD]
    float* Vt = Ks + 64 * APAD;            // [64][APAD]
    int*   msk = (int*)(Vt + 64 * APAD);   // [64]

    int tid  = threadIdx.x;
    int warp = tid >> 5, lane = tid & 31;
    int g = lane >> 2, q = lane & 3;
    int row0 = warp * 16;
    int q0 = blockIdx.x * 128;
    int h  = blockIdx.y;
    int b  = blockIdx.z;

    {
        int r  = tid >> 1;
        int c0 = (tid & 1) * 32;
        const float* qp = QKV + (size_t)(b*SEQ + q0 + r) * QKVSTR + h*DHEAD + c0;
        float* qd = &Qs[r * APAD + c0];
        #pragma unroll
        for (int i = 0; i < 8; i++) {
            float4 v = *(const float4*)(qp + i * 4);
            qd[i*4+0] = __uint_as_float(f2tf(v.x * 0.125f));
            qd[i*4+1] = __uint_as_float(f2tf(v.y * 0.125f));
            qd[i*4+2] = __uint_as_float(f2tf(v.z * 0.125f));
            qd[i*4+3] = __uint_as_float(f2tf(v.w * 0.125f));
        }
    }

    float m_r[2] = {NEG_BIG, NEG_BIG};
    float l_r[2] = {0.f, 0.f};
    float o[8][4];
    #pragma unroll
    for (int nv = 0; nv < 8; nv++)
        #pragma unroll
        for (int r = 0; r < 4; r++) o[nv][r] = 0.f;

    int base = lane & ~3;

    for (int t0 = 0; t0 < SEQ; t0 += 64) {
        {
            int key = tid >> 2;
            int cb  = (tid & 3) * 16;
            const float* kp = QKV + (size_t)(b*SEQ + t0 + key) * QKVSTR + DMODEL + h*DHEAD;
            uint32_t kd = s2u(&Ks[key * APAD]);
            #pragma unroll
            for (int i = 0; i < 4; i++)
                cp16(kd + (cb + i * 4) * 4, kp + cb + i * 4);
        }
        CP_COMMIT();
        {
            int key = tid >> 2;
            int db  = (tid & 3) * 16;
            const float* vp = QKV + (size_t)(b*SEQ + t0 + key) * QKVSTR + 2*DMODEL + h*DHEAD + db;
            #pragma unroll
            for (int i = 0; i < 4; i++) {
                float4 v = *(const float4*)(vp + i * 4);
                Vt[(db + i*4 + 0) * APAD + key] = __uint_as_float(f2tf(v.x));
                Vt[(db + i*4 + 1) * APAD + key] = __uint_as_float(f2tf(v.y));
                Vt[(db + i*4 + 2) * APAD + key] = __uint_as_float(f2tf(v.z));
                Vt[(db + i*4 + 3) * APAD + key] = __uint_as_float(f2tf(v.w));
            }
        }
        if (tid < 64) msk[tid] = mask[b*SEQ + t0 + tid];
        CP_WAIT(0);
        __syncthreads();

        float sc[8][4];
        #pragma unroll
        for (int nj = 0; nj < 8; nj++)
            #pragma unroll
            for (int r = 0; r < 4; r++) sc[nj][r] = 0.f;

        #pragma unroll
        for (int ks = 0; ks < 8; ks++) {
            const float* ap = &Qs[(row0 + g) * APAD + ks * 8 + q];
            uint32_t a0 = __float_as_uint(ap[0]);
            uint32_t a1 = __float_as_uint(ap[8 * APAD]);
            uint32_t a2 = __float_as_uint(ap[4]);
            uint32_t a3 = __float_as_uint(ap[8 * APAD + 4]);
            #pragma unroll
            for (int nj = 0; nj < 8; nj++) {
                const float* bp = &Ks[(nj * 8 + g) * APAD + ks * 8 + q];
                mma_tf32(sc[nj], a0, a1, a2, a3,
                         __float_as_uint(bp[0]), __float_as_uint(bp[4]));
            }
        }

        #pragma unroll
        for (int nj = 0; nj < 8; nj++) {
            int c0 = nj * 8 + 2 * q;
            if (msk[c0]     == 0) { sc[nj][0] = NEG_BIG; sc[nj][2] = NEG_BIG; }
            if (msk[c0 + 1] == 0) { sc[nj][1] = NEG_BIG; sc[nj][3] = NEG_BIG; }
        }

        float mx0 = NEG_BIG, mx1 = NEG_BIG;
        #pragma unroll
        for (int nj = 0; nj < 8; nj++) {
            mx0 = fmaxf(mx0, fmaxf(sc[nj][0], sc[nj][1]));
            mx1 = fmaxf(mx1, fmaxf(sc[nj][2], sc[nj][3]));
        }
        mx0 = fmaxf(mx0, __shfl_xor_sync(0xffffffffu, mx0, 1));
        mx0 = fmaxf(mx0, __shfl_xor_sync(0xffffffffu, mx0, 2));
        mx1 = fmaxf(mx1, __shfl_xor_sync(0xffffffffu, mx1, 1));
        mx1 = fmaxf(mx1, __shfl_xor_sync(0xffffffffu, mx1, 2));
        float mn0 = fmaxf(m_r[0], mx0);
        float mn1 = fmaxf(m_r[1], mx1);
        float fac0 = __expf(m_r[0] - mn0);
        float fac1 = __expf(m_r[1] - mn1);

        float sum0 = 0.f, sum1 = 0.f;
        #pragma unroll
        for (int nj = 0; nj < 8; nj++) {
            sc[nj][0] = __expf(sc[nj][0] - mn0);
            sc[nj][1] = __expf(sc[nj][1] - mn0);
            sc[nj][2] = __expf(sc[nj][2] - mn1);
            sc[nj][3] = __expf(sc[nj][3] - mn1);
            sum0 += sc[nj][0] + sc[nj][1];
            sum1 += sc[nj][2] + sc[nj][3];
        }
        sum0 += __shfl_xor_sync(0xffffffffu, sum0, 1);
        sum0 += __shfl_xor_sync(0xffffffffu, sum0, 2);
        sum1 += __shfl_xor_sync(0xffffffffu, sum1, 1);
        sum1 += __shfl_xor_sync(0xffffffffu, sum1, 2);

        l_r[0] = l_r[0] * fac0 + sum0;  m_r[0] = mn0;
        l_r[1] = l_r[1] * fac1 + sum1;  m_r[1] = mn1;

        #pragma unroll
        for (int nv = 0; nv < 8; nv++) {
            o[nv][0] *= fac0; o[nv][1] *= fac0;
            o[nv][2] *= fac1; o[nv][3] *= fac1;
        }

        #pragma unroll
        for (int ks = 0; ks < 8; ks++) {
            int sl = base | (q >> 1);
            int sh = base | ((q >> 1) + 2);
            float vl0 = __shfl_sync(0xffffffffu, sc[ks][0], sl);
            float vh0 = __shfl_sync(0xffffffffu, sc[ks][1], sl);
            float ul0 = __shfl_sync(0xffffffffu, sc[ks][0], sh);
            float uh0 = __shfl_sync(0xffffffffu, sc[ks][1], sh);
            float vl1 = __shfl_sync(0xffffffffu, sc[ks][2], sl);
            float vh1 = __shfl_sync(0xffffffffu, sc[ks][3], sl);
            float ul1 = __shfl_sync(0xffffffffu, sc[ks][2], sh);
            float uh1 = __shfl_sync(0xffffffffu, sc[ks][3], sh);
            uint32_t A0 = f2tf((q & 1) ? vh0 : vl0);
            uint32_t A2 = f2tf((q & 1) ? uh0 : ul0);
            uint32_t A1 = f2tf((q & 1) ? vh1 : vl1);
            uint32_t A3 = f2tf((q & 1) ? uh1 : ul1);
            #pragma unroll
            for (int nv = 0; nv < 8; nv++) {
                const float* bp = &Vt[(nv * 8 + g) * APAD + ks * 8 + q];
                mma_tf32(o[nv], A0, A1, A2, A3,
                         __float_as_uint(bp[0]), __float_as_uint(bp[4]));
            }
        }
        __syncthreads();
    }

    float inv0 = 1.0f / l_r[0];
    float inv1 = 1.0f / l_r[1];
    int r0 = q0 + row0 + g;
    int r1 = r0 + 8;
    #pragma unroll
    for (int nv = 0; nv < 8; nv++) {
        int col = h * DHEAD + nv * 8 + 2 * q;
        float2 w0, w1;
        w0.x = o[nv][0] * inv0; w0.y = o[nv][1] * inv0;
        w1.x = o[nv][2] * inv1; w1.y = o[nv][3] * inv1;
        *(float2*)(O + (size_t)(b*SEQ + r0) * DMODEL + col) = w0;
        *(float2*)(O + (size_t)(b*SEQ + r1) * DMODEL + col) = w1;
    }
}

// =======================================================================
// launch
// =======================================================================
extern "C" void kernel_launch(void* const* d_in, const int* in_sizes, int n_in,
                              void* d_out, int out_size)
{
    const float* x     = (const float*)d_in[0];
    const int*   mask  = (const int*)  d_in[1];
    const float* wq    = (const float*)d_in[2];
    const float* bq    = (const float*)d_in[3];
    const float* wk    = (const float*)d_in[4];
    const float* bk    = (const float*)d_in[5];
    const float* wv    = (const float*)d_in[6];
    const float* bv    = (const float*)d_in[7];
    const float* wo    = (const float*)d_in[8];
    const float* bo    = (const float*)d_in[9];
    const float* ln1_g = (const float*)d_in[10];
    const float* ln1_b = (const float*)d_in[11];
    const float* ln2_g = (const float*)d_in[12];
    const float* ln2_b = (const float*)d_in[13];
    const float* w1    = (const float*)d_in[14];
    const float* b1    = (const float*)d_in[15];
    const float* w2    = (const float*)d_in[16];
    const float* b2    = (const float*)d_in[17];
    float* out = (float*)d_out;

    float *H, *QKV, *CTX, *X2, *FF, *Wqkv, *Wo, *W1, *W2, *Bqkv;
    cudaGetSymbolAddress((void**)&H,    g_H);
    cudaGetSymbolAddress((void**)&QKV,  g_QKV);
    cudaGetSymbolAddress((void**)&CTX,  g_CTX);
    cudaGetSymbolAddress((void**)&X2,   g_X2);
    cudaGetSymbolAddress((void**)&FF,   g_FF);
    cudaGetSymbolAddress((void**)&Wqkv, g_Wqkv);
    cudaGetSymbolAddress((void**)&Wo,   g_Wo);
    cudaGetSymbolAddress((void**)&W1,   g_W1);
    cudaGetSymbolAddress((void**)&W2,   g_W2);
    cudaGetSymbolAddress((void**)&Bqkv, g_Bqkv);

    cudaFuncSetAttribute(gemm_mma, cudaFuncAttributeMaxDynamicSharedMemorySize, GEMM_SMEM);
    cudaFuncSetAttribute(attn_mma, cudaFuncAttributeMaxDynamicSharedMemorySize, ATTN_SMEM);

    dim3 tb(32, 8);
    transpose_tf32<<<dim3(DMODEL/32, DMODEL/32), tb>>>(wq, Wqkv,                   DMODEL, DMODEL);
    transpose_tf32<<<dim3(DMODEL/32, DMODEL/32), tb>>>(wk, Wqkv + DMODEL*DMODEL,   DMODEL, DMODEL);
    transpose_tf32<<<dim3(DMODEL/32, DMODEL/32), tb>>>(wv, Wqkv + 2*DMODEL*DMODEL, DMODEL, DMODEL);
    transpose_tf32<<<dim3(DMODEL/32, DMODEL/32), tb>>>(wo, Wo, DMODEL, DMODEL);
    transpose_tf32<<<dim3(FFDIM/32,  DMODEL/32), tb>>>(w1, W1, DMODEL, FFDIM);
    transpose_tf32<<<dim3(DMODEL/32, FFDIM/32),  tb>>>(w2, W2, FFDIM, DMODEL);
    concat_bias<<<QKVN/256, 256>>>(bq, bk, bv, Bqkv);

    // residual 1: pre-LN attention
    ln_kernel<<<MTOK, 256>>>(x, ln1_g, ln1_b, H);
    gemm_mma<<<dim3(QKVN/BN, MTOK/BM), 256, GEMM_SMEM>>>(H, Wqkv, Bqkv, nullptr, QKV,
                                                         MTOK, QKVN, DMODEL, 0);
    attn_mma<<<dim3(SEQ/128, NHEADS, BATCH), 256, ATTN_SMEM>>>(QKV, mask, CTX);
    gemm_mma<<<dim3(DMODEL/BN, MTOK/BM), 256, GEMM_SMEM>>>(CTX, Wo, bo, x, X2,
                                                           MTOK, DMODEL, DMODEL, 0);

    // residual 2: pre-LN feed-forward
    ln_kernel<<<MTOK, 256>>>(X2, ln2_g, ln2_b, H);
    gemm_mma<<<dim3(FFDIM/BN, MTOK/BM), 256, GEMM_SMEM>>>(H, W1, b1, nullptr, FF,
                                                          MTOK, FFDIM, DMODEL, 1);
    gemm_mma<<<dim3(DMODEL/BN, MTOK/BM), 256, GEMM_SMEM>>>(FF, W2, b2, X2, out,
                                                           MTOK, DMODEL, FFDIM, 0);
}

// round 8
// speedup vs baseline: 3.2299x; 1.1249x over previous
#include <cuda_runtime.h>
#include <cuda_bf16.h>
#include <math.h>
#include <stdint.h>

// ---------------- problem constants ----------------
#define BATCH   2
#define SEQ     2048
#define DMODEL  1024
#define NHEADS  16
#define DHEAD   64
#define FFDIM   4096
#define MTOK    (BATCH * SEQ)          // 4096 token rows
#define QKVN    (3 * DMODEL)           // 3072
#define QKVSTR  3072

// ---------------- scratch (device globals; no allocation) ----------------
__device__ float g_H   [MTOK * DMODEL];
__device__ float g_QKV [MTOK * QKVN];
__device__ float g_CTX [MTOK * DMODEL];
__device__ float g_X2  [MTOK * DMODEL];
__device__ float g_FF  [MTOK * FFDIM];
__device__ float g_Wqkv[QKVN  * DMODEL];
__device__ float g_Wo  [DMODEL * DMODEL];
__device__ float g_W1  [FFDIM * DMODEL];
__device__ float g_W2  [DMODEL * FFDIM];
__device__ float g_Bqkv[QKVN];

__device__ __forceinline__ uint32_t s2u(const void* p) {
    uint32_t a;
    asm("{ .reg .u64 t; cvta.to.shared.u64 t, %1; cvt.u32.u64 %0, t; }" : "=r"(a) : "l"(p));
    return a;
}
__device__ __forceinline__ uint32_t f2tf(float x) {
    uint32_t r; asm("cvt.rna.tf32.f32 %0, %1;" : "=r"(r) : "f"(x)); return r;
}
__device__ __forceinline__ void cp16(uint32_t dst, const void* src) {
    asm volatile("cp.async.cg.shared.global [%0], [%1], 16;" :: "r"(dst), "l"(src));
}
#define CP_COMMIT() asm volatile("cp.async.commit_group;" ::: "memory")
#define CP_WAIT(n)  asm volatile("cp.async.wait_group %0;" :: "n"(n) : "memory")

__device__ __forceinline__ void mma_tf32(float c[4], uint32_t a0, uint32_t a1,
                                         uint32_t a2, uint32_t a3,
                                         uint32_t b0, uint32_t b1)
{
    asm volatile(
        "mma.sync.aligned.m16n8k8.row.col.f32.tf32.tf32.f32 "
        "{%0,%1,%2,%3}, {%4,%5,%6,%7}, {%8,%9}, {%0,%1,%2,%3};"
        : "+f"(c[0]), "+f"(c[1]), "+f"(c[2]), "+f"(c[3])
        : "r"(a0), "r"(a1), "r"(a2), "r"(a3), "r"(b0), "r"(b1));
}

// =======================================================================
// weight transpose + tf32 round
// =======================================================================
__global__ void transpose_tf32(const float* __restrict__ in, float* __restrict__ out,
                               int K, int N)
{
    __shared__ float tile[32][33];
    int n0 = blockIdx.x * 32, k0 = blockIdx.y * 32;
    int tx = threadIdx.x, ty = threadIdx.y;
    #pragma unroll
    for (int j = 0; j < 32; j += 8)
        tile[ty + j][tx] = in[(size_t)(k0 + ty + j) * N + n0 + tx];
    __syncthreads();
    #pragma unroll
    for (int j = 0; j < 32; j += 8)
        out[(size_t)(n0 + ty + j) * K + k0 + tx] = __uint_as_float(f2tf(tile[tx][ty + j]));
}

__global__ void concat_bias(const float* __restrict__ a, const float* __restrict__ b,
                            const float* __restrict__ c, float* __restrict__ o)
{
    int i = blockIdx.x * blockDim.x + threadIdx.x;
    if (i < QKVN)
        o[i] = (i < DMODEL) ? a[i] : (i < 2 * DMODEL ? b[i - DMODEL] : c[i - 2 * DMODEL]);
}

// =======================================================================
// LayerNorm
// =======================================================================
__global__ void ln_kernel(const float* __restrict__ x,
                          const float* __restrict__ gamma,
                          const float* __restrict__ beta,
                          float* __restrict__ out)
{
    int row = blockIdx.x;
    int tid = threadIdx.x;
    const float* xr = x + (size_t)row * DMODEL;

    float4 v = *(const float4*)(xr + tid * 4);
    float s  = v.x + v.y + v.z + v.w;
    float sq = v.x*v.x + v.y*v.y + v.z*v.z + v.w*v.w;
    #pragma unroll
    for (int off = 16; off > 0; off >>= 1) {
        s  += __shfl_xor_sync(0xffffffffu, s,  off);
        sq += __shfl_xor_sync(0xffffffffu, sq, off);
    }
    __shared__ float ssum[8], ssq[8];
    int wid = tid >> 5, lane = tid & 31;
    if (lane == 0) { ssum[wid] = s; ssq[wid] = sq; }
    __syncthreads();
    float tot = 0.f, totq = 0.f;
    #pragma unroll
    for (int w = 0; w < 8; w++) { tot += ssum[w]; totq += ssq[w]; }

    const float invN = 1.0f / (float)DMODEL;
    float mean = tot * invN;
    float var  = totq * invN - mean * mean;
    float inv  = rsqrtf(var + 1e-5f);

    float4 g4 = *(const float4*)(gamma + tid * 4);
    float4 b4 = *(const float4*)(beta  + tid * 4);
    float4 o;
    o.x = (v.x - mean) * inv * g4.x + b4.x;
    o.y = (v.y - mean) * inv * g4.y + b4.y;
    o.z = (v.z - mean) * inv * g4.z + b4.z;
    o.w = (v.w - mean) * inv * g4.w + b4.w;
    *(float4*)(out + (size_t)row * DMODEL + tid * 4) = o;
}

// =======================================================================
// tf32 mma.sync GEMM: C[M,N] = A[M,K] @ Wt[N,K]^T + bias (+resid)(relu)
// block tile 128x256, BK=32; 8 warps 2x4; warp tile 64x64 (mi=4, ni=8).
// 4-stage cp.async pipeline, ONE __syncthreads per K-iteration.
// PAD=36 -> all fragment loads bank-conflict-free.
// =======================================================================
#define BM 128
#define BN 256
#define BK 32
#define PAD 36
#define A_FLOATS (128 * PAD)
#define B_FLOATS (256 * PAD)
#define STG_FLOATS (A_FLOATS + B_FLOATS)
#define NSTAGE 4
#define GEMM_SMEM (NSTAGE * STG_FLOATS * 4)     // 221184 B

__global__ __launch_bounds__(256, 1)
void gemm_mma(const float* __restrict__ A, const float* __restrict__ Wt,
              const float* __restrict__ bias, const float* __restrict__ resid,
              float* __restrict__ C, int M, int N, int K, int relu)
{
    extern __shared__ float smem[];

    int tid  = threadIdx.x;
    int warp = tid >> 5, lane = tid & 31;
    int wm = warp >> 2;          // 0..1  -> 64-row group
    int wn = warp & 3;           // 0..3  -> 64-col group
    int g  = lane >> 2;          // 0..7
    int q  = lane & 3;           // 0..3
    int bm = blockIdx.y * BM;
    int bn = blockIdx.x * BN;

    // staging map: thread -> (row, 4-float col)
    int s_row = tid >> 3;              // 0..31 (+32*i)
    int s_kq  = (tid & 7) * 4;         // 0,4,...,28

    const int KT = K / BK;

    auto stage = [&](int st, int kt) {
        float* As = smem + st * STG_FLOATS;
        float* Bs = As + A_FLOATS;
        uint32_t aBase = s2u(As);
        uint32_t bBase = s2u(Bs);
        const float* ag = A  + (size_t)(bm + s_row) * K + kt * BK + s_kq;
        const float* bg = Wt + (size_t)(bn + s_row) * K + kt * BK + s_kq;
        #pragma unroll
        for (int i = 0; i < 4; i++)   // A: 128 rows
            cp16(aBase + ((s_row + i * 32) * PAD + s_kq) * 4, ag + (size_t)(i * 32) * K);
        #pragma unroll
        for (int i = 0; i < 8; i++)   // B: 256 rows
            cp16(bBase + ((s_row + i * 32) * PAD + s_kq) * 4, bg + (size_t)(i * 32) * K);
    };

    float c[4][8][4];
    #pragma unroll
    for (int mi = 0; mi < 4; mi++)
        #pragma unroll
        for (int ni = 0; ni < 8; ni++)
            #pragma unroll
            for (int r = 0; r < 4; r++) c[mi][ni][r] = 0.f;

    // prologue: stages 0..2
    stage(0, 0); CP_COMMIT();
    stage(1, 1); CP_COMMIT();
    stage(2, 2); CP_COMMIT();

    for (int kt = 0; kt < KT; kt++) {
        CP_WAIT(2);               // stage kt complete (2 younger groups in flight)
        __syncthreads();          // all warps done reading buffer (kt-1)%4, data visible

        if (kt + 3 < KT) stage((kt + 3) & 3, kt + 3);
        CP_COMMIT();              // commit (possibly empty) to keep group accounting

        const float* Af = smem + (kt & 3) * STG_FLOATS + (wm * 64 + g) * PAD + q;
        const float* Bf = smem + (kt & 3) * STG_FLOATS + A_FLOATS + (wn * 64 + g) * PAD + q;
        #pragma unroll
        for (int ks = 0; ks < 4; ks++) {
            uint32_t a[4][4], b[8][2];
            #pragma unroll
            for (int mi = 0; mi < 4; mi++) {
                const float* p = Af + mi * 16 * PAD + ks * 8;
                a[mi][0] = __float_as_uint(p[0]);
                a[mi][1] = __float_as_uint(p[8 * PAD]);
                a[mi][2] = __float_as_uint(p[4]);
                a[mi][3] = __float_as_uint(p[8 * PAD + 4]);
            }
            #pragma unroll
            for (int ni = 0; ni < 8; ni++) {
                const float* p = Bf + ni * 8 * PAD + ks * 8;
                b[ni][0] = __float_as_uint(p[0]);
                b[ni][1] = __float_as_uint(p[4]);
            }
            #pragma unroll
            for (int mi = 0; mi < 4; mi++)
                #pragma unroll
                for (int ni = 0; ni < 8; ni++)
                    mma_tf32(c[mi][ni], a[mi][0], a[mi][1], a[mi][2], a[mi][3],
                             b[ni][0], b[ni][1]);
        }
    }

    // ---- epilogue ----
    #pragma unroll
    for (int ni = 0; ni < 8; ni++) {
        int col = bn + wn * 64 + ni * 8 + q * 2;
        float2 bv = *(const float2*)(bias + col);
        #pragma unroll
        for (int mi = 0; mi < 4; mi++) {
            int row = bm + wm * 64 + mi * 16 + g;
            #pragma unroll
            for (int half = 0; half < 2; half++) {
                int r = row + half * 8;
                float2 o;
                o.x = c[mi][ni][half * 2 + 0] + bv.x;
                o.y = c[mi][ni][half * 2 + 1] + bv.y;
                if (resid) {
                    float2 rv = *(const float2*)(resid + (size_t)r * N + col);
                    o.x += rv.x; o.y += rv.y;
                }
                if (relu) { o.x = fmaxf(o.x, 0.f); o.y = fmaxf(o.y, 0.f); }
                *(float2*)(C + (size_t)r * N + col) = o;
            }
        }
    }
}

// =======================================================================
// tf32 tensor-core flash attention (identical to round 5/7 — passing)
// =======================================================================
#define APAD 68
#define NEG_BIG (-1e30f)
#define ATTN_SMEM ((128 + 64 + 64) * APAD * 4 + 64 * 4)

__global__ __launch_bounds__(256, 1)
void attn_mma(const float* __restrict__ QKV, const int* __restrict__ mask,
              float* __restrict__ O)
{
    extern __shared__ float sm[];
    float* Qs = sm;                        // [128][APAD]
    float* Ks = Qs + 128 * APAD;           // [64][APAD]
    float* Vt = Ks + 64 * APAD;            // [64][APAD]
    int*   msk = (int*)(Vt + 64 * APAD);   // [64]

    int tid  = threadIdx.x;
    int warp = tid >> 5, lane = tid & 31;
    int g = lane >> 2, q = lane & 3;
    int row0 = warp * 16;
    int q0 = blockIdx.x * 128;
    int h  = blockIdx.y;
    int b  = blockIdx.z;

    {
        int r  = tid >> 1;
        int c0 = (tid & 1) * 32;
        const float* qp = QKV + (size_t)(b*SEQ + q0 + r) * QKVSTR + h*DHEAD + c0;
        float* qd = &Qs[r * APAD + c0];
        #pragma unroll
        for (int i = 0; i < 8; i++) {
            float4 v = *(const float4*)(qp + i * 4);
            qd[i*4+0] = __uint_as_float(f2tf(v.x * 0.125f));
            qd[i*4+1] = __uint_as_float(f2tf(v.y * 0.125f));
            qd[i*4+2] = __uint_as_float(f2tf(v.z * 0.125f));
            qd[i*4+3] = __uint_as_float(f2tf(v.w * 0.125f));
        }
    }

    float m_r[2] = {NEG_BIG, NEG_BIG};
    float l_r[2] = {0.f, 0.f};
    float o[8][4];
    #pragma unroll
    for (int nv = 0; nv < 8; nv++)
        #pragma unroll
        for (int r = 0; r < 4; r++) o[nv][r] = 0.f;

    int base = lane & ~3;

    for (int t0 = 0; t0 < SEQ; t0 += 64) {
        {
            int key = tid >> 2;
            int cb  = (tid & 3) * 16;
            const float* kp = QKV + (size_t)(b*SEQ + t0 + key) * QKVSTR + DMODEL + h*DHEAD;
            uint32_t kd = s2u(&Ks[key * APAD]);
            #pragma unroll
            for (int i = 0; i < 4; i++)
                cp16(kd + (cb + i * 4) * 4, kp + cb + i * 4);
        }
        CP_COMMIT();
        {
            int key = tid >> 2;
            int db  = (tid & 3) * 16;
            const float* vp = QKV + (size_t)(b*SEQ + t0 + key) * QKVSTR + 2*DMODEL + h*DHEAD + db;
            #pragma unroll
            for (int i = 0; i < 4; i++) {
                float4 v = *(const float4*)(vp + i * 4);
                Vt[(db + i*4 + 0) * APAD + key] = __uint_as_float(f2tf(v.x));
                Vt[(db + i*4 + 1) * APAD + key] = __uint_as_float(f2tf(v.y));
                Vt[(db + i*4 + 2) * APAD + key] = __uint_as_float(f2tf(v.z));
                Vt[(db + i*4 + 3) * APAD + key] = __uint_as_float(f2tf(v.w));
            }
        }
        if (tid < 64) msk[tid] = mask[b*SEQ + t0 + tid];
        CP_WAIT(0);
        __syncthreads();

        float sc[8][4];
        #pragma unroll
        for (int nj = 0; nj < 8; nj++)
            #pragma unroll
            for (int r = 0; r < 4; r++) sc[nj][r] = 0.f;

        #pragma unroll
        for (int ks = 0; ks < 8; ks++) {
            const float* ap = &Qs[(row0 + g) * APAD + ks * 8 + q];
            uint32_t a0 = __float_as_uint(ap[0]);
            uint32_t a1 = __float_as_uint(ap[8 * APAD]);
            uint32_t a2 = __float_as_uint(ap[4]);
            uint32_t a3 = __float_as_uint(ap[8 * APAD + 4]);
            #pragma unroll
            for (int nj = 0; nj < 8; nj++) {
                const float* bp = &Ks[(nj * 8 + g) * APAD + ks * 8 + q];
                mma_tf32(sc[nj], a0, a1, a2, a3,
                         __float_as_uint(bp[0]), __float_as_uint(bp[4]));
            }
        }

        #pragma unroll
        for (int nj = 0; nj < 8; nj++) {
            int c0 = nj * 8 + 2 * q;
            if (msk[c0]     == 0) { sc[nj][0] = NEG_BIG; sc[nj][2] = NEG_BIG; }
            if (msk[c0 + 1] == 0) { sc[nj][1] = NEG_BIG; sc[nj][3] = NEG_BIG; }
        }

        float mx0 = NEG_BIG, mx1 = NEG_BIG;
        #pragma unroll
        for (int nj = 0; nj < 8; nj++) {
            mx0 = fmaxf(mx0, fmaxf(sc[nj][0], sc[nj][1]));
            mx1 = fmaxf(mx1, fmaxf(sc[nj][2], sc[nj][3]));
        }
        mx0 = fmaxf(mx0, __shfl_xor_sync(0xffffffffu, mx0, 1));
        mx0 = fmaxf(mx0, __shfl_xor_sync(0xffffffffu, mx0, 2));
        mx1 = fmaxf(mx1, __shfl_xor_sync(0xffffffffu, mx1, 1));
        mx1 = fmaxf(mx1, __shfl_xor_sync(0xffffffffu, mx1, 2));
        float mn0 = fmaxf(m_r[0], mx0);
        float mn1 = fmaxf(m_r[1], mx1);
        float fac0 = __expf(m_r[0] - mn0);
        float fac1 = __expf(m_r[1] - mn1);

        float sum0 = 0.f, sum1 = 0.f;
        #pragma unroll
        for (int nj = 0; nj < 8; nj++) {
            sc[nj][0] = __expf(sc[nj][0] - mn0);
            sc[nj][1] = __expf(sc[nj][1] - mn0);
            sc[nj][2] = __expf(sc[nj][2] - mn1);
            sc[nj][3] = __expf(sc[nj][3] - mn1);
            sum0 += sc[nj][0] + sc[nj][1];
            sum1 += sc[nj][2] + sc[nj][3];
        }
        sum0 += __shfl_xor_sync(0xffffffffu, sum0, 1);
        sum0 += __shfl_xor_sync(0xffffffffu, sum0, 2);
        sum1 += __shfl_xor_sync(0xffffffffu, sum1, 1);
        sum1 += __shfl_xor_sync(0xffffffffu, sum1, 2);

        l_r[0] = l_r[0] * fac0 + sum0;  m_r[0] = mn0;
        l_r[1] = l_r[1] * fac1 + sum1;  m_r[1] = mn1;

        #pragma unroll
        for (int nv = 0; nv < 8; nv++) {
            o[nv][0] *= fac0; o[nv][1] *= fac0;
            o[nv][2] *= fac1; o[nv][3] *= fac1;
        }

        #pragma unroll
        for (int ks = 0; ks < 8; ks++) {
            int sl = base | (q >> 1);
            int sh = base | ((q >> 1) + 2);
            float vl0 = __shfl_sync(0xffffffffu, sc[ks][0], sl);
            float vh0 = __shfl_sync(0xffffffffu, sc[ks][1], sl);
            float ul0 = __shfl_sync(0xffffffffu, sc[ks][0], sh);
            float uh0 = __shfl_sync(0xffffffffu, sc[ks][1], sh);
            float vl1 = __shfl_sync(0xffffffffu, sc[ks][2], sl);
            float vh1 = __shfl_sync(0xffffffffu, sc[ks][3], sl);
            float ul1 = __shfl_sync(0xffffffffu, sc[ks][2], sh);
            float uh1 = __shfl_sync(0xffffffffu, sc[ks][3], sh);
            uint32_t A0 = f2tf((q & 1) ? vh0 : vl0);
            uint32_t A2 = f2tf((q & 1) ? uh0 : ul0);
            uint32_t A1 = f2tf((q & 1) ? vh1 : vl1);
            uint32_t A3 = f2tf((q & 1) ? uh1 : ul1);
            #pragma unroll
            for (int nv = 0; nv < 8; nv++) {
                const float* bp = &Vt[(nv * 8 + g) * APAD + ks * 8 + q];
                mma_tf32(o[nv], A0, A1, A2, A3,
                         __float_as_uint(bp[0]), __float_as_uint(bp[4]));
            }
        }
        __syncthreads();
    }

    float inv0 = 1.0f / l_r[0];
    float inv1 = 1.0f / l_r[1];
    int r0 = q0 + row0 + g;
    int r1 = r0 + 8;
    #pragma unroll
    for (int nv = 0; nv < 8; nv++) {
        int col = h * DHEAD + nv * 8 + 2 * q;
        float2 w0, w1;
        w0.x = o[nv][0] * inv0; w0.y = o[nv][1] * inv0;
        w1.x = o[nv][2] * inv1; w1.y = o[nv][3] * inv1;
        *(float2*)(O + (size_t)(b*SEQ + r0) * DMODEL + col) = w0;
        *(float2*)(O + (size_t)(b*SEQ + r1) * DMODEL + col) = w1;
    }
}

// =======================================================================
// launch
// =======================================================================
extern "C" void kernel_launch(void* const* d_in, const int* in_sizes, int n_in,
                              void* d_out, int out_size)
{
    const float* x     = (const float*)d_in[0];
    const int*   mask  = (const int*)  d_in[1];
    const float* wq    = (const float*)d_in[2];
    const float* bq    = (const float*)d_in[3];
    const float* wk    = (const float*)d_in[4];
    const float* bk    = (const float*)d_in[5];
    const float* wv    = (const float*)d_in[6];
    const float* bv    = (const float*)d_in[7];
    const float* wo    = (const float*)d_in[8];
    const float* bo    = (const float*)d_in[9];
    const float* ln1_g = (const float*)d_in[10];
    const float* ln1_b = (const float*)d_in[11];
    const float* ln2_g = (const float*)d_in[12];
    const float* ln2_b = (const float*)d_in[13];
    const float* w1    = (const float*)d_in[14];
    const float* b1    = (const float*)d_in[15];
    const float* w2    = (const float*)d_in[16];
    const float* b2    = (const float*)d_in[17];
    float* out = (float*)d_out;

    float *H, *QKV, *CTX, *X2, *FF, *Wqkv, *Wo, *W1, *W2, *Bqkv;
    cudaGetSymbolAddress((void**)&H,    g_H);
    cudaGetSymbolAddress((void**)&QKV,  g_QKV);
    cudaGetSymbolAddress((void**)&CTX,  g_CTX);
    cudaGetSymbolAddress((void**)&X2,   g_X2);
    cudaGetSymbolAddress((void**)&FF,   g_FF);
    cudaGetSymbolAddress((void**)&Wqkv, g_Wqkv);
    cudaGetSymbolAddress((void**)&Wo,   g_Wo);
    cudaGetSymbolAddress((void**)&W1,   g_W1);
    cudaGetSymbolAddress((void**)&W2,   g_W2);
    cudaGetSymbolAddress((void**)&Bqkv, g_Bqkv);

    cudaFuncSetAttribute(gemm_mma, cudaFuncAttributeMaxDynamicSharedMemorySize, GEMM_SMEM);
    cudaFuncSetAttribute(attn_mma, cudaFuncAttributeMaxDynamicSharedMemorySize, ATTN_SMEM);

    dim3 tb(32, 8);
    transpose_tf32<<<dim3(DMODEL/32, DMODEL/32), tb>>>(wq, Wqkv,                   DMODEL, DMODEL);
    transpose_tf32<<<dim3(DMODEL/32, DMODEL/32), tb>>>(wk, Wqkv + DMODEL*DMODEL,   DMODEL, DMODEL);
    transpose_tf32<<<dim3(DMODEL/32, DMODEL/32), tb>>>(wv, Wqkv + 2*DMODEL*DMODEL, DMODEL, DMODEL);
    transpose_tf32<<<dim3(DMODEL/32, DMODEL/32), tb>>>(wo, Wo, DMODEL, DMODEL);
    transpose_tf32<<<dim3(FFDIM/32,  DMODEL/32), tb>>>(w1, W1, DMODEL, FFDIM);
    transpose_tf32<<<dim3(DMODEL/32, FFDIM/32),  tb>>>(w2, W2, FFDIM, DMODEL);
    concat_bias<<<QKVN/256, 256>>>(bq, bk, bv, Bqkv);

    // residual 1: pre-LN attention
    ln_kernel<<<MTOK, 256>>>(x, ln1_g, ln1_b, H);
    gemm_mma<<<dim3(QKVN/BN, MTOK/BM), 256, GEMM_SMEM>>>(H, Wqkv, Bqkv, nullptr, QKV,
                                                         MTOK, QKVN, DMODEL, 0);
    attn_mma<<<dim3(SEQ/128, NHEADS, BATCH), 256, ATTN_SMEM>>>(QKV, mask, CTX);
    gemm_mma<<<dim3(DMODEL/BN, MTOK/BM), 256, GEMM_SMEM>>>(CTX, Wo, bo, x, X2,
                                                           MTOK, DMODEL, DMODEL, 0);

    // residual 2: pre-LN feed-forward
    ln_kernel<<<MTOK, 256>>>(X2, ln2_g, ln2_b, H);
    gemm_mma<<<dim3(FFDIM/BN, MTOK/BM), 256, GEMM_SMEM>>>(H, W1, b1, nullptr, FF,
                                                          MTOK, FFDIM, DMODEL, 1);
    gemm_mma<<<dim3(DMODEL/BN, MTOK/BM), 256, GEMM_SMEM>>>(FF, W2, b2, X2, out,
                                                           MTOK, DMODEL, FFDIM, 0);
}